// round 1
// baseline (speedup 1.0000x reference)
#include <cuda_runtime.h>
#include <math.h>

#define BSZ   2
#define SEQ   2048
#define EMB   4096
#define NH    32
#define NKVH  8
#define HD    128
#define GROUPS (NH / NKVH)
#define MROWS (BSZ * SEQ)          // 4096
#define QDIM  (NH * HD)            // 4096
#define KVDIM (NKVH * HD)          // 1024

// Scratch (device globals: allocation-free contract)
__device__ float g_Q[(size_t)MROWS * QDIM];    // 64 MB
__device__ float g_K[(size_t)MROWS * KVDIM];   // 16 MB
__device__ float g_V[(size_t)MROWS * KVDIM];   // 16 MB
__device__ float g_AO[(size_t)MROWS * QDIM];   // 64 MB

// ---------------------------------------------------------------------------
// Tiled SGEMM: C[M,N] = A[M,K] @ B[K,N], all row-major, dims multiples of 128/8
// 128x128 tile, BK=8, 256 threads, 8x8 micro-tile per thread.
// ---------------------------------------------------------------------------
__global__ __launch_bounds__(256) void sgemm128(const float* __restrict__ A,
                                                const float* __restrict__ B,
                                                float* __restrict__ C,
                                                int M, int N, int K)
{
    __shared__ float As[8][128];   // transposed A tile: As[k][m]
    __shared__ float Bs[8][128];
    const int tid = threadIdx.x;
    const int bm = blockIdx.y * 128;
    const int bn = blockIdx.x * 128;
    const int arow = tid >> 1;           // 0..127
    const int acol = (tid & 1) * 4;      // 0 or 4
    const int brow = tid >> 5;           // 0..7
    const int bcol = (tid & 31) * 4;     // 0..124
    const int ty = tid >> 4;             // 0..15
    const int tx = tid & 15;             // 0..15

    const float* Ap = A + (size_t)(bm + arow) * K + acol;
    const float* Bp = B + (size_t)brow * N + bn + bcol;

    float acc[8][8];
#pragma unroll
    for (int i = 0; i < 8; i++)
#pragma unroll
        for (int j = 0; j < 8; j++) acc[i][j] = 0.0f;

    for (int k0 = 0; k0 < K; k0 += 8) {
        float4 a4 = *(const float4*)(Ap + k0);
        float4 b4 = *(const float4*)(Bp + (size_t)k0 * N);
        __syncthreads();
        As[acol + 0][arow] = a4.x;
        As[acol + 1][arow] = a4.y;
        As[acol + 2][arow] = a4.z;
        As[acol + 3][arow] = a4.w;
        *(float4*)&Bs[brow][bcol] = b4;
        __syncthreads();
#pragma unroll
        for (int kk = 0; kk < 8; kk++) {
            float ar[8], br[8];
            *(float4*)(ar)     = *(const float4*)&As[kk][ty * 8];
            *(float4*)(ar + 4) = *(const float4*)&As[kk][ty * 8 + 4];
            *(float4*)(br)     = *(const float4*)&Bs[kk][tx * 8];
            *(float4*)(br + 4) = *(const float4*)&Bs[kk][tx * 8 + 4];
#pragma unroll
            for (int i = 0; i < 8; i++)
#pragma unroll
                for (int j = 0; j < 8; j++)
                    acc[i][j] = fmaf(ar[i], br[j], acc[i][j]);
        }
    }

#pragma unroll
    for (int i = 0; i < 8; i++) {
        float* Crow = C + (size_t)(bm + ty * 8 + i) * N + bn + tx * 8;
        float4 o0 = make_float4(acc[i][0], acc[i][1], acc[i][2], acc[i][3]);
        float4 o1 = make_float4(acc[i][4], acc[i][5], acc[i][6], acc[i][7]);
        *(float4*)(Crow)     = o0;
        *(float4*)(Crow + 4) = o1;
    }
}

// ---------------------------------------------------------------------------
// RoPE in-place on X[MROWS, nheads*HD]. position = row % SEQ (reference uses
// arange positions). half-rotation convention matching _rotate_half.
// ---------------------------------------------------------------------------
__global__ void rope_kernel(float* __restrict__ X, int nheads, int total)
{
    int idx = blockIdx.x * blockDim.x + threadIdx.x;
    if (idx >= total) return;
    int d   = idx & 63;
    int h   = (idx >> 6) % nheads;
    int row = idx / (64 * nheads);
    float p   = (float)(row % SEQ);
    float inv = powf(10000.0f, -(float)(2 * d) / 128.0f);
    float ang = p * inv;
    float s, c;
    sincosf(ang, &s, &c);
    size_t base = (size_t)row * ((size_t)nheads * HD) + (size_t)h * HD + d;
    float x1 = X[base];
    float x2 = X[base + 64];
    X[base]      = x1 * c - x2 * s;
    X[base + 64] = x2 * c + x1 * s;
}

// ---------------------------------------------------------------------------
// Flash attention (causal, GQA): one block per (q-tile of 64, head, batch).
// 256 threads. Online softmax. K and V share one smem buffer (aliased).
// ---------------------------------------------------------------------------
#define FLASH_SMEM_FLOATS (128*64 + 128*64 + 64*65 + 64*3)
#define FLASH_SMEM_BYTES  (FLASH_SMEM_FLOATS * 4)

__global__ __launch_bounds__(256) void flash_kernel(const float* __restrict__ Q,
                                                    const float* __restrict__ K,
                                                    const float* __restrict__ V,
                                                    float* __restrict__ O)
{
    extern __shared__ float smem[];
    float* QsT  = smem;                  // [128][64]  (d-major, transposed)
    float* KVs  = QsT + 128 * 64;        // KsT [128][64]  OR  Vs [64][128]
    float* Ps   = KVs + 128 * 64;        // [64][65] padded scores/probs
    float* mrow = Ps + 64 * 65;          // [64]
    float* lrow = mrow + 64;             // [64]
    float* arow = lrow + 64;             // [64]

    const int qi  = blockIdx.x;          // 0..31
    const int h   = blockIdx.y;          // 0..31
    const int b   = blockIdx.z;          // 0..1
    const int kvh = h / GROUPS;
    const int tid = threadIdx.x;
    const int tr = tid >> 4, tc = tid & 15;   // S-stage / PV-stage tile coords
    const int srow = tid >> 2, sc = tid & 3;  // softmax coords (4 lanes/row)

    const float* Qb  = Q + (size_t)(b * SEQ + qi * 64) * QDIM + h * HD;
    const float* Kb0 = K + (size_t)(b * SEQ) * KVDIM + kvh * HD;
    const float* Vb0 = V + (size_t)(b * SEQ) * KVDIM + kvh * HD;

    // Load Q tile transposed: QsT[d][row]
#pragma unroll
    for (int l = 0; l < 8; l++) {
        int idx = l * 256 + tid;
        int r = idx & 63, d4 = idx >> 6;
        float4 v4 = *(const float4*)(Qb + (size_t)r * QDIM + d4 * 4);
        QsT[(d4 * 4 + 0) * 64 + r] = v4.x;
        QsT[(d4 * 4 + 1) * 64 + r] = v4.y;
        QsT[(d4 * 4 + 2) * 64 + r] = v4.z;
        QsT[(d4 * 4 + 3) * 64 + r] = v4.w;
    }
    if (tid < 64) { mrow[tid] = -INFINITY; lrow[tid] = 0.0f; }

    float acc[4][8];
#pragma unroll
    for (int i = 0; i < 4; i++)
#pragma unroll
        for (int j = 0; j < 8; j++) acc[i][j] = 0.0f;

    __syncthreads();

    for (int kb = 0; kb <= qi; kb++) {
        // ---- load K tile transposed into KVs: KsT[d][krow] ----
        const float* Kb = Kb0 + (size_t)(kb * 64) * KVDIM;
#pragma unroll
        for (int l = 0; l < 8; l++) {
            int idx = l * 256 + tid;
            int r = idx & 63, d4 = idx >> 6;
            float4 v4 = *(const float4*)(Kb + (size_t)r * KVDIM + d4 * 4);
            KVs[(d4 * 4 + 0) * 64 + r] = v4.x;
            KVs[(d4 * 4 + 1) * 64 + r] = v4.y;
            KVs[(d4 * 4 + 2) * 64 + r] = v4.z;
            KVs[(d4 * 4 + 3) * 64 + r] = v4.w;
        }
        __syncthreads();

        // ---- S = Q @ K^T  (64x64, 4x4 per thread) ----
        float sacc[4][4];
#pragma unroll
        for (int i = 0; i < 4; i++)
#pragma unroll
            for (int j = 0; j < 4; j++) sacc[i][j] = 0.0f;

#pragma unroll 8
        for (int kk = 0; kk < 128; kk++) {
            float4 qv = *(const float4*)(QsT + kk * 64 + tr * 4);
            float4 kv = *(const float4*)(KVs + kk * 64 + tc * 4);
            float qa[4] = {qv.x, qv.y, qv.z, qv.w};
            float ka[4] = {kv.x, kv.y, kv.z, kv.w};
#pragma unroll
            for (int i = 0; i < 4; i++)
#pragma unroll
                for (int j = 0; j < 4; j++)
                    sacc[i][j] = fmaf(qa[i], ka[j], sacc[i][j]);
        }
        const float scale = 0.08838834764831845f;  // 1/sqrt(128)
#pragma unroll
        for (int i = 0; i < 4; i++)
#pragma unroll
            for (int j = 0; j < 4; j++)
                Ps[(tr * 4 + i) * 65 + tc * 4 + j] = sacc[i][j] * scale;
        __syncthreads();

        // ---- online softmax (4 lanes per row, 16 cols each) ----
        {
            int qg = qi * 64 + srow;
            float mold = mrow[srow];
            float mx = -INFINITY;
#pragma unroll
            for (int jj = 0; jj < 16; jj++) {
                int col = sc * 16 + jj;
                if (kb * 64 + col <= qg) mx = fmaxf(mx, Ps[srow * 65 + col]);
            }
            mx = fmaxf(mx, __shfl_xor_sync(0xffffffffu, mx, 1));
            mx = fmaxf(mx, __shfl_xor_sync(0xffffffffu, mx, 2));
            float mnew = fmaxf(mold, mx);
            float ls = 0.0f;
#pragma unroll
            for (int jj = 0; jj < 16; jj++) {
                int col = sc * 16 + jj;
                float p = 0.0f;
                if (kb * 64 + col <= qg)
                    p = __expf(Ps[srow * 65 + col] - mnew);
                Ps[srow * 65 + col] = p;
                ls += p;
            }
            ls += __shfl_xor_sync(0xffffffffu, ls, 1);
            ls += __shfl_xor_sync(0xffffffffu, ls, 2);
            if (sc == 0) {
                float alpha = __expf(mold - mnew);
                mrow[srow] = mnew;
                lrow[srow] = lrow[srow] * alpha + ls;
                arow[srow] = alpha;
            }
        }
        __syncthreads();

        // ---- load V tile row-major into KVs (aliased): Vs[krow][d] ----
        const float* Vb = Vb0 + (size_t)(kb * 64) * KVDIM;
#pragma unroll
        for (int l = 0; l < 8; l++) {
            int idx = l * 256 + tid;
            int r = idx >> 5, d4 = idx & 31;
            float4 v4 = *(const float4*)(Vb + (size_t)r * KVDIM + d4 * 4);
            *(float4*)(KVs + r * 128 + d4 * 4) = v4;
        }
        __syncthreads();

        // ---- O = O*alpha + P @ V  (4 rows x 8 dims per thread) ----
        {
            float a0 = arow[tr * 4 + 0];
            float a1 = arow[tr * 4 + 1];
            float a2 = arow[tr * 4 + 2];
            float a3 = arow[tr * 4 + 3];
#pragma unroll
            for (int j = 0; j < 8; j++) {
                acc[0][j] *= a0; acc[1][j] *= a1;
                acc[2][j] *= a2; acc[3][j] *= a3;
            }
#pragma unroll 4
            for (int k = 0; k < 64; k++) {
                float p0 = Ps[(tr * 4 + 0) * 65 + k];
                float p1 = Ps[(tr * 4 + 1) * 65 + k];
                float p2 = Ps[(tr * 4 + 2) * 65 + k];
                float p3 = Ps[(tr * 4 + 3) * 65 + k];
                float4 va = *(const float4*)(KVs + k * 128 + tc * 8);
                float4 vb = *(const float4*)(KVs + k * 128 + tc * 8 + 4);
                float v[8] = {va.x, va.y, va.z, va.w, vb.x, vb.y, vb.z, vb.w};
#pragma unroll
                for (int j = 0; j < 8; j++) {
                    acc[0][j] = fmaf(p0, v[j], acc[0][j]);
                    acc[1][j] = fmaf(p1, v[j], acc[1][j]);
                    acc[2][j] = fmaf(p2, v[j], acc[2][j]);
                    acc[3][j] = fmaf(p3, v[j], acc[3][j]);
                }
            }
        }
        __syncthreads();
    }

    // ---- epilogue: divide by l, write (b, s, h, d) layout ----
    float* Ob = O + (size_t)(b * SEQ + qi * 64) * QDIM + h * HD;
#pragma unroll
    for (int i = 0; i < 4; i++) {
        int r = tr * 4 + i;
        float inv = 1.0f / lrow[r];
        float4 o0 = make_float4(acc[i][0] * inv, acc[i][1] * inv,
                                acc[i][2] * inv, acc[i][3] * inv);
        float4 o1 = make_float4(acc[i][4] * inv, acc[i][5] * inv,
                                acc[i][6] * inv, acc[i][7] * inv);
        *(float4*)(Ob + (size_t)r * QDIM + tc * 8)     = o0;
        *(float4*)(Ob + (size_t)r * QDIM + tc * 8 + 4) = o1;
    }
}

// ---------------------------------------------------------------------------
// Launch: QKV proj -> RoPE -> flash attention -> O proj
// ---------------------------------------------------------------------------
extern "C" void kernel_launch(void* const* d_in, const int* in_sizes, int n_in,
                              void* d_out, int out_size)
{
    const float* query = (const float*)d_in[0];
    const float* key   = (const float*)d_in[1];
    const float* value = (const float*)d_in[2];
    // d_in[3] position_ids: reference is arange(S) broadcast; computed in-kernel.
    // d_in[4] src_mask: causal tril; implemented directly.
    const float* Wq = (const float*)d_in[5];
    const float* Wk = (const float*)d_in[6];
    const float* Wv = (const float*)d_in[7];
    const float* Wo = (const float*)d_in[8];
    float* out = (float*)d_out;

    float *pQ, *pK, *pV, *pAO;
    cudaGetSymbolAddress((void**)&pQ,  g_Q);
    cudaGetSymbolAddress((void**)&pK,  g_K);
    cudaGetSymbolAddress((void**)&pV,  g_V);
    cudaGetSymbolAddress((void**)&pAO, g_AO);

    cudaFuncSetAttribute(flash_kernel,
                         cudaFuncAttributeMaxDynamicSharedMemorySize,
                         FLASH_SMEM_BYTES);

    dim3 blk(256);

    // Projections
    sgemm128<<<dim3(QDIM  / 128, MROWS / 128), blk>>>(query, Wq, pQ, MROWS, QDIM,  EMB);
    sgemm128<<<dim3(KVDIM / 128, MROWS / 128), blk>>>(key,   Wk, pK, MROWS, KVDIM, EMB);
    sgemm128<<<dim3(KVDIM / 128, MROWS / 128), blk>>>(value, Wv, pV, MROWS, KVDIM, EMB);

    // RoPE
    int totq = MROWS * NH * 64;
    rope_kernel<<<(totq + 255) / 256, 256>>>(pQ, NH, totq);
    int totk = MROWS * NKVH * 64;
    rope_kernel<<<(totk + 255) / 256, 256>>>(pK, NKVH, totk);

    // Attention
    flash_kernel<<<dim3(SEQ / 64, NH, BSZ), blk, FLASH_SMEM_BYTES>>>(pQ, pK, pV, pAO);

    // Output projection
    sgemm128<<<dim3(EMB / 128, MROWS / 128), blk>>>(pAO, Wo, out, MROWS, EMB, QDIM);
}

// round 3
// speedup vs baseline: 2.3763x; 2.3763x over previous
#include <cuda_runtime.h>
#include <math.h>
#include <stdint.h>

#define BSZ   2
#define SEQ   2048
#define EMB   4096
#define NH    32
#define NKVH  8
#define HD    128
#define GROUPS (NH / NKVH)
#define MROWS (BSZ * SEQ)          // 4096
#define QDIM  (NH * HD)            // 4096
#define KVDIM (NKVH * HD)          // 1024

// Scratch (device globals: allocation-free contract)
__device__ float g_Q[(size_t)MROWS * QDIM];     // 64 MB
__device__ float g_K[(size_t)MROWS * KVDIM];    // 16 MB
__device__ float g_V[(size_t)MROWS * KVDIM];    // 16 MB
__device__ float g_AO[(size_t)MROWS * QDIM];    // 64 MB
__device__ float g_WqT[(size_t)QDIM * EMB];     // [N][K]
__device__ float g_WkT[(size_t)KVDIM * EMB];
__device__ float g_WvT[(size_t)KVDIM * EMB];
__device__ float g_WoT[(size_t)EMB * QDIM];

// ---------------------------------------------------------------------------
// Helpers
// ---------------------------------------------------------------------------
__device__ __forceinline__ uint32_t smem_u32(const void* p) {
    uint32_t a;
    asm("{ .reg .u64 t; cvta.to.shared.u64 t, %1; cvt.u32.u64 %0, t; }" : "=r"(a) : "l"(p));
    return a;
}
__device__ __forceinline__ uint32_t f2tf32(float x) {
    uint32_t r;
    asm("cvt.rna.tf32.f32 %0, %1;" : "=r"(r) : "f"(x));
    return r;
}
__device__ __forceinline__ void cpasync16(uint32_t dst, const void* src) {
    asm volatile("cp.async.cg.shared.global [%0], [%1], 16;" :: "r"(dst), "l"(src) : "memory");
}
#define CP_COMMIT() asm volatile("cp.async.commit_group;" ::: "memory")
#define CP_WAIT(n)  asm volatile("cp.async.wait_group %0;" :: "n"(n) : "memory")

__device__ __forceinline__ void mma_tf32(float* d, const uint32_t* a, const uint32_t* b) {
    asm volatile("mma.sync.aligned.m16n8k8.row.col.f32.tf32.tf32.f32 "
        "{%0,%1,%2,%3}, {%4,%5,%6,%7}, {%8,%9}, {%0,%1,%2,%3};"
        : "+f"(d[0]), "+f"(d[1]), "+f"(d[2]), "+f"(d[3])
        : "r"(a[0]), "r"(a[1]), "r"(a[2]), "r"(a[3]), "r"(b[0]), "r"(b[1]));
}

// ---------------------------------------------------------------------------
// Plain transpose: out[c][r] = in[r][c]; in is R x C.
// ---------------------------------------------------------------------------
__global__ void transpose_w(const float* __restrict__ in, float* __restrict__ out,
                            int R, int C)
{
    __shared__ float t[32][33];
    int bc = blockIdx.x * 32, br = blockIdx.y * 32;
    int x = threadIdx.x, y = threadIdx.y;
#pragma unroll
    for (int j = 0; j < 32; j += 8)
        t[y + j][x] = in[(size_t)(br + y + j) * C + bc + x];
    __syncthreads();
#pragma unroll
    for (int j = 0; j < 32; j += 8)
        out[(size_t)(bc + y + j) * R + br + x] = t[x][y + j];
}

// ---------------------------------------------------------------------------
// tf32 tensor-core GEMM via mma.sync: C[M,N] = A[M,K] @ BT[N,K]^T
// 128x128 CTA tile, BK=32, 8 warps (warp tile 64x32), cp.async double buffer.
// Row pad = 36 floats (16B aligned, conflict-free fragment loads).
// ---------------------------------------------------------------------------
#define ROWP 36
#define STAGE_FLOATS (2 * 128 * ROWP)             // A block + B block
#define GEMM_SMEM_BYTES (2 * STAGE_FLOATS * 4)    // 73728

__global__ __launch_bounds__(256, 2) void gemm_tf32mma(const float* __restrict__ A,
                                                       const float* __restrict__ BT,
                                                       float* __restrict__ C,
                                                       int M, int N, int K)
{
    extern __shared__ float sm[];
    const uint32_t sb = smem_u32(sm);

    const int tid  = threadIdx.x;
    const int wid  = tid >> 5, lane = tid & 31;
    const int g    = lane >> 2, tig = lane & 3;
    const int wm   = (wid >> 2) * 64;       // warp row offset (0,64)
    const int wn   = (wid & 3) * 32;        // warp col offset (0..96)
    const int bm   = blockIdx.y * 128, bn = blockIdx.x * 128;

    const float* Ab0 = A  + (size_t)bm * K;
    const float* Bb0 = BT + (size_t)bn * K;

    // async tile loader: 1024 16B-chunks per operand, 4 per thread
    auto load_tile = [&](int c, int s) {
        const float* Ab = Ab0 + c * 32;
        const float* Bb = Bb0 + c * 32;
        uint32_t sa  = sb + (uint32_t)s * (STAGE_FLOATS * 4);
        uint32_t sbb = sa + 128 * ROWP * 4;
#pragma unroll
        for (int l = 0; l < 4; l++) {
            int chunk = l * 256 + tid;
            int row = chunk >> 3;
            int c4  = (chunk & 7) * 4;
            cpasync16(sa  + (uint32_t)(row * ROWP + c4) * 4, Ab + (size_t)row * K + c4);
            cpasync16(sbb + (uint32_t)(row * ROWP + c4) * 4, Bb + (size_t)row * K + c4);
        }
        CP_COMMIT();
    };

    float acc[4][4][4];
#pragma unroll
    for (int mi = 0; mi < 4; mi++)
#pragma unroll
        for (int ni = 0; ni < 4; ni++)
#pragma unroll
            for (int r = 0; r < 4; r++) acc[mi][ni][r] = 0.0f;

    const int iters = K / 32;
    load_tile(0, 0);

    for (int c = 0; c < iters; c++) {
        const int s = c & 1;
        if (c + 1 < iters) load_tile(c + 1, s ^ 1);
        if (c + 1 < iters) { CP_WAIT(1); } else { CP_WAIT(0); }
        __syncthreads();

        const float* As = sm + (size_t)s * STAGE_FLOATS;
        const float* Bs = As + 128 * ROWP;

#pragma unroll
        for (int ks = 0; ks < 4; ks++) {
            const int kb = ks * 8;
            uint32_t af[4][4], bf[4][2];
#pragma unroll
            for (int mi = 0; mi < 4; mi++) {
                int r = wm + mi * 16 + g;
                af[mi][0] = f2tf32(As[r * ROWP + kb + tig]);
                af[mi][1] = f2tf32(As[(r + 8) * ROWP + kb + tig]);
                af[mi][2] = f2tf32(As[r * ROWP + kb + tig + 4]);
                af[mi][3] = f2tf32(As[(r + 8) * ROWP + kb + tig + 4]);
            }
#pragma unroll
            for (int ni = 0; ni < 4; ni++) {
                int rn = wn + ni * 8 + g;
                bf[ni][0] = f2tf32(Bs[rn * ROWP + kb + tig]);
                bf[ni][1] = f2tf32(Bs[rn * ROWP + kb + tig + 4]);
            }
#pragma unroll
            for (int mi = 0; mi < 4; mi++)
#pragma unroll
                for (int ni = 0; ni < 4; ni++)
                    mma_tf32(acc[mi][ni], af[mi], bf[ni]);
        }
        __syncthreads();
    }

    // epilogue: c0(g,2t) c1(g,2t+1) c2(g+8,2t) c3(g+8,2t+1)
#pragma unroll
    for (int mi = 0; mi < 4; mi++) {
        int row0 = bm + wm + mi * 16 + g;
#pragma unroll
        for (int ni = 0; ni < 4; ni++) {
            int col = bn + wn + ni * 8 + tig * 2;
            float2 v0 = make_float2(acc[mi][ni][0], acc[mi][ni][1]);
            float2 v1 = make_float2(acc[mi][ni][2], acc[mi][ni][3]);
            *(float2*)(C + (size_t)row0 * N + col)       = v0;
            *(float2*)(C + (size_t)(row0 + 8) * N + col) = v1;
        }
    }
}

// ---------------------------------------------------------------------------
// RoPE in-place on X[MROWS, nheads*HD]. position = row % SEQ.
// ---------------------------------------------------------------------------
__global__ void rope_kernel(float* __restrict__ X, int nheads, int total)
{
    int idx = blockIdx.x * blockDim.x + threadIdx.x;
    if (idx >= total) return;
    int d   = idx & 63;
    int h   = (idx >> 6) % nheads;
    int row = idx / (64 * nheads);
    float p   = (float)(row % SEQ);
    float inv = powf(10000.0f, -(float)(2 * d) / 128.0f);
    float ang = p * inv;
    float s, c;
    sincosf(ang, &s, &c);
    size_t base = (size_t)row * ((size_t)nheads * HD) + (size_t)h * HD + d;
    float x1 = X[base];
    float x2 = X[base + 64];
    X[base]      = x1 * c - x2 * s;
    X[base + 64] = x2 * c + x1 * s;
}

// ---------------------------------------------------------------------------
// Flash attention (causal, GQA): one block per (q-tile of 64, head, batch).
// ---------------------------------------------------------------------------
#define FLASH_SMEM_FLOATS (128*64 + 128*64 + 64*65 + 64*3)
#define FLASH_SMEM_BYTES  (FLASH_SMEM_FLOATS * 4)

__global__ __launch_bounds__(256) void flash_kernel(const float* __restrict__ Q,
                                                    const float* __restrict__ K,
                                                    const float* __restrict__ V,
                                                    float* __restrict__ O)
{
    extern __shared__ float fsm[];
    float* QsT  = fsm;
    float* KVs  = QsT + 128 * 64;
    float* Ps   = KVs + 128 * 64;
    float* mrow = Ps + 64 * 65;
    float* lrow = mrow + 64;
    float* arow = lrow + 64;

    const int qi  = blockIdx.x;
    const int h   = blockIdx.y;
    const int b   = blockIdx.z;
    const int kvh = h / GROUPS;
    const int tid = threadIdx.x;
    const int tr = tid >> 4, tc = tid & 15;
    const int srow = tid >> 2, sc = tid & 3;

    const float* Qb  = Q + (size_t)(b * SEQ + qi * 64) * QDIM + h * HD;
    const float* Kb0 = K + (size_t)(b * SEQ) * KVDIM + kvh * HD;
    const float* Vb0 = V + (size_t)(b * SEQ) * KVDIM + kvh * HD;

#pragma unroll
    for (int l = 0; l < 8; l++) {
        int idx = l * 256 + tid;
        int r = idx & 63, d4 = idx >> 6;
        float4 v4 = *(const float4*)(Qb + (size_t)r * QDIM + d4 * 4);
        QsT[(d4 * 4 + 0) * 64 + r] = v4.x;
        QsT[(d4 * 4 + 1) * 64 + r] = v4.y;
        QsT[(d4 * 4 + 2) * 64 + r] = v4.z;
        QsT[(d4 * 4 + 3) * 64 + r] = v4.w;
    }
    if (tid < 64) { mrow[tid] = -INFINITY; lrow[tid] = 0.0f; }

    float acc[4][8];
#pragma unroll
    for (int i = 0; i < 4; i++)
#pragma unroll
        for (int j = 0; j < 8; j++) acc[i][j] = 0.0f;

    __syncthreads();

    for (int kb = 0; kb <= qi; kb++) {
        const float* Kb = Kb0 + (size_t)(kb * 64) * KVDIM;
#pragma unroll
        for (int l = 0; l < 8; l++) {
            int idx = l * 256 + tid;
            int r = idx & 63, d4 = idx >> 6;
            float4 v4 = *(const float4*)(Kb + (size_t)r * KVDIM + d4 * 4);
            KVs[(d4 * 4 + 0) * 64 + r] = v4.x;
            KVs[(d4 * 4 + 1) * 64 + r] = v4.y;
            KVs[(d4 * 4 + 2) * 64 + r] = v4.z;
            KVs[(d4 * 4 + 3) * 64 + r] = v4.w;
        }
        __syncthreads();

        float sacc[4][4];
#pragma unroll
        for (int i = 0; i < 4; i++)
#pragma unroll
            for (int j = 0; j < 4; j++) sacc[i][j] = 0.0f;

#pragma unroll 8
        for (int kk = 0; kk < 128; kk++) {
            float4 qv = *(const float4*)(QsT + kk * 64 + tr * 4);
            float4 kv = *(const float4*)(KVs + kk * 64 + tc * 4);
            float qa[4] = {qv.x, qv.y, qv.z, qv.w};
            float ka[4] = {kv.x, kv.y, kv.z, kv.w};
#pragma unroll
            for (int i = 0; i < 4; i++)
#pragma unroll
                for (int j = 0; j < 4; j++)
                    sacc[i][j] = fmaf(qa[i], ka[j], sacc[i][j]);
        }
        const float scale = 0.08838834764831845f;
#pragma unroll
        for (int i = 0; i < 4; i++)
#pragma unroll
            for (int j = 0; j < 4; j++)
                Ps[(tr * 4 + i) * 65 + tc * 4 + j] = sacc[i][j] * scale;
        __syncthreads();

        {
            int qg = qi * 64 + srow;
            float mold = mrow[srow];
            float mx = -INFINITY;
#pragma unroll
            for (int jj = 0; jj < 16; jj++) {
                int col = sc * 16 + jj;
                if (kb * 64 + col <= qg) mx = fmaxf(mx, Ps[srow * 65 + col]);
            }
            mx = fmaxf(mx, __shfl_xor_sync(0xffffffffu, mx, 1));
            mx = fmaxf(mx, __shfl_xor_sync(0xffffffffu, mx, 2));
            float mnew = fmaxf(mold, mx);
            float ls = 0.0f;
#pragma unroll
            for (int jj = 0; jj < 16; jj++) {
                int col = sc * 16 + jj;
                float p = 0.0f;
                if (kb * 64 + col <= qg)
                    p = __expf(Ps[srow * 65 + col] - mnew);
                Ps[srow * 65 + col] = p;
                ls += p;
            }
            ls += __shfl_xor_sync(0xffffffffu, ls, 1);
            ls += __shfl_xor_sync(0xffffffffu, ls, 2);
            if (sc == 0) {
                float alpha = __expf(mold - mnew);
                mrow[srow] = mnew;
                lrow[srow] = lrow[srow] * alpha + ls;
                arow[srow] = alpha;
            }
        }
        __syncthreads();

        const float* Vb = Vb0 + (size_t)(kb * 64) * KVDIM;
#pragma unroll
        for (int l = 0; l < 8; l++) {
            int idx = l * 256 + tid;
            int r = idx >> 5, d4 = idx & 31;
            float4 v4 = *(const float4*)(Vb + (size_t)r * KVDIM + d4 * 4);
            *(float4*)(KVs + r * 128 + d4 * 4) = v4;
        }
        __syncthreads();

        {
            float a0 = arow[tr * 4 + 0];
            float a1 = arow[tr * 4 + 1];
            float a2 = arow[tr * 4 + 2];
            float a3 = arow[tr * 4 + 3];
#pragma unroll
            for (int j = 0; j < 8; j++) {
                acc[0][j] *= a0; acc[1][j] *= a1;
                acc[2][j] *= a2; acc[3][j] *= a3;
            }
#pragma unroll 4
            for (int k = 0; k < 64; k++) {
                float p0 = Ps[(tr * 4 + 0) * 65 + k];
                float p1 = Ps[(tr * 4 + 1) * 65 + k];
                float p2 = Ps[(tr * 4 + 2) * 65 + k];
                float p3 = Ps[(tr * 4 + 3) * 65 + k];
                float4 va = *(const float4*)(KVs + k * 128 + tc * 8);
                float4 vb = *(const float4*)(KVs + k * 128 + tc * 8 + 4);
                float v[8] = {va.x, va.y, va.z, va.w, vb.x, vb.y, vb.z, vb.w};
#pragma unroll
                for (int j = 0; j < 8; j++) {
                    acc[0][j] = fmaf(p0, v[j], acc[0][j]);
                    acc[1][j] = fmaf(p1, v[j], acc[1][j]);
                    acc[2][j] = fmaf(p2, v[j], acc[2][j]);
                    acc[3][j] = fmaf(p3, v[j], acc[3][j]);
                }
            }
        }
        __syncthreads();
    }

    float* Ob = O + (size_t)(b * SEQ + qi * 64) * QDIM + h * HD;
#pragma unroll
    for (int i = 0; i < 4; i++) {
        int r = tr * 4 + i;
        float inv = 1.0f / lrow[r];
        float4 o0 = make_float4(acc[i][0] * inv, acc[i][1] * inv,
                                acc[i][2] * inv, acc[i][3] * inv);
        float4 o1 = make_float4(acc[i][4] * inv, acc[i][5] * inv,
                                acc[i][6] * inv, acc[i][7] * inv);
        *(float4*)(Ob + (size_t)r * QDIM + tc * 8)     = o0;
        *(float4*)(Ob + (size_t)r * QDIM + tc * 8 + 4) = o1;
    }
}

// ---------------------------------------------------------------------------
// Launch
// ---------------------------------------------------------------------------
extern "C" void kernel_launch(void* const* d_in, const int* in_sizes, int n_in,
                              void* d_out, int out_size)
{
    const float* query = (const float*)d_in[0];
    const float* key   = (const float*)d_in[1];
    const float* value = (const float*)d_in[2];
    const float* Wq = (const float*)d_in[5];
    const float* Wk = (const float*)d_in[6];
    const float* Wv = (const float*)d_in[7];
    const float* Wo = (const float*)d_in[8];
    float* out = (float*)d_out;

    float *pQ, *pK, *pV, *pAO, *pWqT, *pWkT, *pWvT, *pWoT;
    cudaGetSymbolAddress((void**)&pQ,   g_Q);
    cudaGetSymbolAddress((void**)&pK,   g_K);
    cudaGetSymbolAddress((void**)&pV,   g_V);
    cudaGetSymbolAddress((void**)&pAO,  g_AO);
    cudaGetSymbolAddress((void**)&pWqT, g_WqT);
    cudaGetSymbolAddress((void**)&pWkT, g_WkT);
    cudaGetSymbolAddress((void**)&pWvT, g_WvT);
    cudaGetSymbolAddress((void**)&pWoT, g_WoT);

    cudaFuncSetAttribute(flash_kernel, cudaFuncAttributeMaxDynamicSharedMemorySize,
                         FLASH_SMEM_BYTES);
    cudaFuncSetAttribute(gemm_tf32mma, cudaFuncAttributeMaxDynamicSharedMemorySize,
                         GEMM_SMEM_BYTES);

    dim3 tb(32, 8);
    transpose_w<<<dim3(QDIM  / 32, EMB / 32), tb>>>(Wq, pWqT, EMB, QDIM);
    transpose_w<<<dim3(KVDIM / 32, EMB / 32), tb>>>(Wk, pWkT, EMB, KVDIM);
    transpose_w<<<dim3(KVDIM / 32, EMB / 32), tb>>>(Wv, pWvT, EMB, KVDIM);
    transpose_w<<<dim3(EMB   / 32, QDIM / 32), tb>>>(Wo, pWoT, QDIM, EMB);

    gemm_tf32mma<<<dim3(QDIM  / 128, MROWS / 128), 256, GEMM_SMEM_BYTES>>>(query, pWqT, pQ, MROWS, QDIM,  EMB);
    gemm_tf32mma<<<dim3(KVDIM / 128, MROWS / 128), 256, GEMM_SMEM_BYTES>>>(key,   pWkT, pK, MROWS, KVDIM, EMB);
    gemm_tf32mma<<<dim3(KVDIM / 128, MROWS / 128), 256, GEMM_SMEM_BYTES>>>(value, pWvT, pV, MROWS, KVDIM, EMB);

    int totq = MROWS * NH * 64;
    rope_kernel<<<(totq + 255) / 256, 256>>>(pQ, NH, totq);
    int totk = MROWS * NKVH * 64;
    rope_kernel<<<(totk + 255) / 256, 256>>>(pK, NKVH, totk);

    flash_kernel<<<dim3(SEQ / 64, NH, BSZ), 256, FLASH_SMEM_BYTES>>>(pQ, pK, pV, pAO);

    gemm_tf32mma<<<dim3(EMB / 128, MROWS / 128), 256, GEMM_SMEM_BYTES>>>(pAO, pWoT, out, MROWS, EMB, QDIM);
}

// round 4
// speedup vs baseline: 7.0477x; 2.9658x over previous
#include <cuda_runtime.h>
#include <cuda_fp16.h>
#include <math.h>
#include <stdint.h>

#define BSZ   2
#define SEQ   2048
#define EMB   4096
#define NH    32
#define NKVH  8
#define HD    128
#define GROUPS (NH / NKVH)
#define MROWS (BSZ * SEQ)          // 4096
#define QDIM  (NH * HD)            // 4096
#define KVDIM (NKVH * HD)          // 1024

// log2(e)/sqrt(128), folded into Q so softmax uses bare exp2
#define QSCALE 0.12751744f

// Scratch (device globals)
__device__ float  g_Q [(size_t)MROWS * QDIM];    // fp32 gemm outs
__device__ float  g_K [(size_t)MROWS * KVDIM];
__device__ float  g_V [(size_t)MROWS * KVDIM];
__device__ __half g_Ah [(size_t)MROWS * EMB];    // activation half buffer (reused)
__device__ __half g_Qh [(size_t)MROWS * QDIM];
__device__ __half g_Kh [(size_t)MROWS * KVDIM];
__device__ __half g_Vh [(size_t)MROWS * KVDIM];
__device__ __half g_AOh[(size_t)MROWS * QDIM];
__device__ __half g_WqTh[(size_t)QDIM * EMB];    // [N][K] half
__device__ __half g_WkTh[(size_t)KVDIM * EMB];
__device__ __half g_WvTh[(size_t)KVDIM * EMB];
__device__ __half g_WoTh[(size_t)EMB * QDIM];

// ---------------------------------------------------------------------------
// Helpers
// ---------------------------------------------------------------------------
__device__ __forceinline__ uint32_t smem_u32(const void* p) {
    uint32_t a;
    asm("{ .reg .u64 t; cvta.to.shared.u64 t, %1; cvt.u32.u64 %0, t; }" : "=r"(a) : "l"(p));
    return a;
}
__device__ __forceinline__ void cpasync16(uint32_t dst, const void* src) {
    asm volatile("cp.async.cg.shared.global [%0], [%1], 16;" :: "r"(dst), "l"(src) : "memory");
}
#define CP_COMMIT() asm volatile("cp.async.commit_group;" ::: "memory")
#define CP_WAIT(n)  asm volatile("cp.async.wait_group %0;" :: "n"(n) : "memory")

__device__ __forceinline__ void mma_f16(float* d, const uint32_t* a, uint32_t b0, uint32_t b1) {
    asm volatile("mma.sync.aligned.m16n8k16.row.col.f32.f16.f16.f32 "
        "{%0,%1,%2,%3}, {%4,%5,%6,%7}, {%8,%9}, {%0,%1,%2,%3};"
        : "+f"(d[0]), "+f"(d[1]), "+f"(d[2]), "+f"(d[3])
        : "r"(a[0]), "r"(a[1]), "r"(a[2]), "r"(a[3]), "r"(b0), "r"(b1));
}

// ---------------------------------------------------------------------------
// Transpose + fp32->half: out[c][r] = (half)in[r][c]; in is R x C.
// ---------------------------------------------------------------------------
__global__ void transpose_h(const float* __restrict__ in, __half* __restrict__ out,
                            int R, int C)
{
    __shared__ float t[32][33];
    int bc = blockIdx.x * 32, br = blockIdx.y * 32;
    int x = threadIdx.x, y = threadIdx.y;
#pragma unroll
    for (int j = 0; j < 32; j += 8)
        t[y + j][x] = in[(size_t)(br + y + j) * C + bc + x];
    __syncthreads();
#pragma unroll
    for (int j = 0; j < 32; j += 8)
        out[(size_t)(bc + y + j) * R + br + x] = __float2half(t[x][y + j]);
}

// fp32 -> half elementwise (n multiple of 4)
__global__ void conv_f2h(const float* __restrict__ in, __half* __restrict__ out, int n)
{
    int i = (blockIdx.x * blockDim.x + threadIdx.x) * 4;
    if (i >= n) return;
    float4 v = *(const float4*)(in + i);
    *(__half2*)(out + i)     = __floats2half2_rn(v.x, v.y);
    *(__half2*)(out + i + 2) = __floats2half2_rn(v.z, v.w);
}

// ---------------------------------------------------------------------------
// fp16 tensor-core GEMM: C[M,N] = A[M,K] @ BT[N,K]^T, A/BT half, C fp32.
// 128x128 CTA tile, BK=64 halves, 8 warps (warp tile 64x32), cp.async 2-stage.
// smem row pitch 72 halves (144B, 16B-aligned, conflict-free frags).
// ---------------------------------------------------------------------------
#define HP 72
#define STG_HALF (2 * 128 * HP)                 // A+B halves per stage
#define GEMM16_SMEM (2 * STG_HALF * 2)          // 73728 bytes

__global__ __launch_bounds__(256, 2) void gemm_f16(const __half* __restrict__ A,
                                                   const __half* __restrict__ BT,
                                                   float* __restrict__ C,
                                                   int M, int N, int K)
{
    extern __shared__ __half smh[];
    const uint32_t sb = smem_u32(smh);

    const int tid  = threadIdx.x;
    const int wid  = tid >> 5, lane = tid & 31;
    const int g    = lane >> 2, tig = lane & 3;
    const int wm   = (wid >> 2) * 64;
    const int wn   = (wid & 3) * 32;
    const int bm   = blockIdx.y * 128, bn = blockIdx.x * 128;

    const __half* Ab0 = A  + (size_t)bm * K;
    const __half* Bb0 = BT + (size_t)bn * K;

    auto load_tile = [&](int c, int s) {
        const __half* Ab = Ab0 + c * 64;
        const __half* Bb = Bb0 + c * 64;
        uint32_t sa  = sb + (uint32_t)s * (STG_HALF * 2);
        uint32_t sbb = sa + 128 * HP * 2;
#pragma unroll
        for (int l = 0; l < 4; l++) {
            int id = l * 256 + tid;
            int r = id >> 3, c8 = (id & 7) * 8;
            cpasync16(sa  + (uint32_t)(r * HP + c8) * 2, Ab + (size_t)r * K + c8);
            cpasync16(sbb + (uint32_t)(r * HP + c8) * 2, Bb + (size_t)r * K + c8);
        }
        CP_COMMIT();
    };

    float acc[4][4][4];
#pragma unroll
    for (int mi = 0; mi < 4; mi++)
#pragma unroll
        for (int ni = 0; ni < 4; ni++)
#pragma unroll
            for (int r = 0; r < 4; r++) acc[mi][ni][r] = 0.0f;

    const int iters = K / 64;
    load_tile(0, 0);

    for (int c = 0; c < iters; c++) {
        const int s = c & 1;
        if (c + 1 < iters) { load_tile(c + 1, s ^ 1); CP_WAIT(1); }
        else               { CP_WAIT(0); }
        __syncthreads();

        const uint32_t* A32 = (const uint32_t*)(smh + (size_t)s * STG_HALF);
        const uint32_t* B32 = A32 + 128 * HP / 2;

#pragma unroll
        for (int ks = 0; ks < 4; ks++) {
            uint32_t af[4][4], bf[4][2];
#pragma unroll
            for (int mi = 0; mi < 4; mi++) {
                int r = wm + mi * 16 + g;
                af[mi][0] = A32[r * (HP/2) + ks * 8 + tig];
                af[mi][1] = A32[(r + 8) * (HP/2) + ks * 8 + tig];
                af[mi][2] = A32[r * (HP/2) + ks * 8 + tig + 4];
                af[mi][3] = A32[(r + 8) * (HP/2) + ks * 8 + tig + 4];
            }
#pragma unroll
            for (int ni = 0; ni < 4; ni++) {
                int rn = wn + ni * 8 + g;
                bf[ni][0] = B32[rn * (HP/2) + ks * 8 + tig];
                bf[ni][1] = B32[rn * (HP/2) + ks * 8 + tig + 4];
            }
#pragma unroll
            for (int mi = 0; mi < 4; mi++)
#pragma unroll
                for (int ni = 0; ni < 4; ni++)
                    mma_f16(acc[mi][ni], af[mi], bf[ni][0], bf[ni][1]);
        }
        __syncthreads();
    }

#pragma unroll
    for (int mi = 0; mi < 4; mi++) {
        int row0 = bm + wm + mi * 16 + g;
#pragma unroll
        for (int ni = 0; ni < 4; ni++) {
            int col = bn + wn + ni * 8 + tig * 2;
            *(float2*)(C + (size_t)row0 * N + col)       = make_float2(acc[mi][ni][0], acc[mi][ni][1]);
            *(float2*)(C + (size_t)(row0 + 8) * N + col) = make_float2(acc[mi][ni][2], acc[mi][ni][3]);
        }
    }
}

// ---------------------------------------------------------------------------
// RoPE fp32 -> half, optional pre-scale (QSCALE for Q, 1.0 for K).
// position = row % SEQ.
// ---------------------------------------------------------------------------
__global__ void rope_h(const float* __restrict__ X, __half* __restrict__ Y,
                       int nheads, float sc, int total)
{
    int idx = blockIdx.x * blockDim.x + threadIdx.x;
    if (idx >= total) return;
    int d   = idx & 63;
    int h   = (idx >> 6) % nheads;
    int row = idx / (64 * nheads);
    float p   = (float)(row % SEQ);
    float inv = powf(10000.0f, -(float)(2 * d) / 128.0f);
    float ang = p * inv;
    float s, c;
    sincosf(ang, &s, &c);
    size_t base = (size_t)row * ((size_t)nheads * HD) + (size_t)h * HD + d;
    float x1 = X[base];
    float x2 = X[base + 64];
    Y[base]      = __float2half((x1 * c - x2 * s) * sc);
    Y[base + 64] = __float2half((x2 * c + x1 * s) * sc);
}

// ---------------------------------------------------------------------------
// Flash attention v2 (fp16 MMA, causal GQA).
// Q tile 128, K tile 64. 8 warps; warp owns 16 q-rows.
// Q pre-scaled by log2e/sqrt(D) -> softmax = exp2(s - m).
// smem halves: Qs[128][136], Ks[64][136], Vt[128][72], Ps[128][72]
// ---------------------------------------------------------------------------
#define QP 136           // Q/K row pitch (halves)
#define VP 72            // Vt/Ps row pitch (halves)
#define FL2_SMEM ((128*QP + 64*QP + 128*VP + 128*VP) * 2)   // 89088 bytes

__global__ __launch_bounds__(256, 1) void flash2(const __half* __restrict__ Q,
                                                 const __half* __restrict__ K,
                                                 const __half* __restrict__ V,
                                                 __half* __restrict__ O)
{
    extern __shared__ __half hs[];
    __half* Qs = hs;                       // [128][136]
    __half* Ks = Qs + 128 * QP;            // [64][136]
    __half* Vt = Ks + 64 * QP;             // [128][72]  (V^T: [d][key])
    __half* Ps = Vt + 128 * VP;            // [128][72]

    const uint32_t* Q32 = (const uint32_t*)Qs;
    const uint32_t* K32 = (const uint32_t*)Ks;
    const uint32_t* V32 = (const uint32_t*)Vt;
    const uint32_t* P32r = (const uint32_t*)Ps;
    __half2* P2 = (__half2*)Ps;

    const int qi  = blockIdx.x;            // 0..15
    const int h   = blockIdx.y;
    const int b   = blockIdx.z;
    const int kvh = h / GROUPS;
    const int tid = threadIdx.x;
    const int wid = tid >> 5, lane = tid & 31;
    const int g   = lane >> 2, tig = lane & 3;
    const int wq  = wid * 16;

    const __half* Qg = Q + (size_t)(b * SEQ + qi * 128) * QDIM + h * HD;
    const __half* Kg = K + (size_t)(b * SEQ) * KVDIM + kvh * HD;
    const __half* Vg = V + (size_t)(b * SEQ) * KVDIM + kvh * HD;

    // load Q tile (128 x 128 halves)
#pragma unroll
    for (int l = 0; l < 8; l++) {
        int id = l * 256 + tid;
        int r = id >> 4, c8 = (id & 15) * 8;
        *(uint4*)(Qs + r * QP + c8) = *(const uint4*)(Qg + (size_t)r * QDIM + c8);
    }

    float m0 = -INFINITY, m1 = -INFINITY, l0 = 0.f, l1 = 0.f;
    float oa[16][4];
#pragma unroll
    for (int ni = 0; ni < 16; ni++)
#pragma unroll
        for (int r = 0; r < 4; r++) oa[ni][r] = 0.f;

    const int kmax = 2 * qi + 2;
    for (int kb = 0; kb < kmax; kb++) {
        // ---- load K tile (64 x 128) and V^T tile (128 x 64) ----
        const __half* Kt = Kg + (size_t)(kb * 64) * KVDIM;
#pragma unroll
        for (int l = 0; l < 4; l++) {
            int id = l * 256 + tid;
            int r = id >> 4, c8 = (id & 15) * 8;
            *(uint4*)(Ks + r * QP + c8) = *(const uint4*)(Kt + (size_t)r * KVDIM + c8);
        }
        const __half* Vg2 = Vg + (size_t)(kb * 64) * KVDIM;
#pragma unroll
        for (int l = 0; l < 16; l++) {
            int id = l * 256 + tid;
            int key = id >> 6, d2 = id & 63;
            __half2 v = *(const __half2*)(Vg2 + (size_t)key * KVDIM + d2 * 2);
            Vt[(d2 * 2 + 0) * VP + key] = __low2half(v);
            Vt[(d2 * 2 + 1) * VP + key] = __high2half(v);
        }
        __syncthreads();

        // ---- S = Q K^T (warp: 16 x 64), fp32 accum ----
        float sa[8][4];
#pragma unroll
        for (int ni = 0; ni < 8; ni++)
#pragma unroll
            for (int r = 0; r < 4; r++) sa[ni][r] = 0.f;

#pragma unroll
        for (int ks = 0; ks < 8; ks++) {
            uint32_t a[4];
            a[0] = Q32[(wq + g) * (QP/2) + ks * 8 + tig];
            a[1] = Q32[(wq + g + 8) * (QP/2) + ks * 8 + tig];
            a[2] = Q32[(wq + g) * (QP/2) + ks * 8 + tig + 4];
            a[3] = Q32[(wq + g + 8) * (QP/2) + ks * 8 + tig + 4];
#pragma unroll
            for (int ni = 0; ni < 8; ni++) {
                uint32_t b0 = K32[(ni * 8 + g) * (QP/2) + ks * 8 + tig];
                uint32_t b1 = K32[(ni * 8 + g) * (QP/2) + ks * 8 + tig + 4];
                mma_f16(sa[ni], a, b0, b1);
            }
        }

        // ---- causal mask (only the 2 diagonal tiles) ----
        if (kb >= 2 * qi) {
            int r0 = qi * 128 + wq + g;
#pragma unroll
            for (int ni = 0; ni < 8; ni++) {
                int c0 = kb * 64 + ni * 8 + 2 * tig;
                if (c0 > r0)         sa[ni][0] = -INFINITY;
                if (c0 + 1 > r0)     sa[ni][1] = -INFINITY;
                if (c0 > r0 + 8)     sa[ni][2] = -INFINITY;
                if (c0 + 1 > r0 + 8) sa[ni][3] = -INFINITY;
            }
        }

        // ---- online softmax (rows g, g+8; quad-redundant state) ----
        float mx0 = -INFINITY, mx1 = -INFINITY;
#pragma unroll
        for (int ni = 0; ni < 8; ni++) {
            mx0 = fmaxf(mx0, fmaxf(sa[ni][0], sa[ni][1]));
            mx1 = fmaxf(mx1, fmaxf(sa[ni][2], sa[ni][3]));
        }
        mx0 = fmaxf(mx0, __shfl_xor_sync(0xffffffffu, mx0, 1));
        mx0 = fmaxf(mx0, __shfl_xor_sync(0xffffffffu, mx0, 2));
        mx1 = fmaxf(mx1, __shfl_xor_sync(0xffffffffu, mx1, 1));
        mx1 = fmaxf(mx1, __shfl_xor_sync(0xffffffffu, mx1, 2));

        float mm0 = fmaxf(m0, mx0), mm1 = fmaxf(m1, mx1);
        float sub0 = (mm0 == -INFINITY) ? 0.f : mm0;
        float sub1 = (mm1 == -INFINITY) ? 0.f : mm1;
        float al0 = exp2f(m0 - sub0);
        float al1 = exp2f(m1 - sub1);
        m0 = mm0; m1 = mm1;

        float ls0 = 0.f, ls1 = 0.f;
#pragma unroll
        for (int ni = 0; ni < 8; ni++) {
            float p0 = exp2f(sa[ni][0] - sub0);
            float p1 = exp2f(sa[ni][1] - sub0);
            float p2 = exp2f(sa[ni][2] - sub1);
            float p3 = exp2f(sa[ni][3] - sub1);
            ls0 += p0 + p1; ls1 += p2 + p3;
            P2[(wq + g) * (VP/2) + ni * 4 + tig]     = __floats2half2_rn(p0, p1);
            P2[(wq + g + 8) * (VP/2) + ni * 4 + tig] = __floats2half2_rn(p2, p3);
        }
        ls0 += __shfl_xor_sync(0xffffffffu, ls0, 1);
        ls0 += __shfl_xor_sync(0xffffffffu, ls0, 2);
        ls1 += __shfl_xor_sync(0xffffffffu, ls1, 1);
        ls1 += __shfl_xor_sync(0xffffffffu, ls1, 2);
        l0 = l0 * al0 + ls0;
        l1 = l1 * al1 + ls1;

#pragma unroll
        for (int ni = 0; ni < 16; ni++) {
            oa[ni][0] *= al0; oa[ni][1] *= al0;
            oa[ni][2] *= al1; oa[ni][3] *= al1;
        }
        __syncwarp();   // Ps visibility across lanes of this warp

        // ---- O += P @ V  (A = Ps rows of this warp, B = Vt) ----
#pragma unroll
        for (int ks = 0; ks < 4; ks++) {
            uint32_t a[4];
            a[0] = P32r[(wq + g) * (VP/2) + ks * 8 + tig];
            a[1] = P32r[(wq + g + 8) * (VP/2) + ks * 8 + tig];
            a[2] = P32r[(wq + g) * (VP/2) + ks * 8 + tig + 4];
            a[3] = P32r[(wq + g + 8) * (VP/2) + ks * 8 + tig + 4];
#pragma unroll
            for (int ni = 0; ni < 16; ni++) {
                uint32_t b0 = V32[(ni * 8 + g) * (VP/2) + ks * 8 + tig];
                uint32_t b1 = V32[(ni * 8 + g) * (VP/2) + ks * 8 + tig + 4];
                mma_f16(oa[ni], a, b0, b1);
            }
        }
        __syncthreads();  // protect K/V smem reuse next iter
    }

    // ---- epilogue: O /= l, write half ----
    float inv0 = 1.0f / l0, inv1 = 1.0f / l1;
    __half* Og = O + (size_t)(b * SEQ + qi * 128 + wq) * QDIM + h * HD;
#pragma unroll
    for (int ni = 0; ni < 16; ni++) {
        int col = ni * 8 + 2 * tig;
        *(__half2*)(Og + (size_t)g * QDIM + col) =
            __floats2half2_rn(oa[ni][0] * inv0, oa[ni][1] * inv0);
        *(__half2*)(Og + (size_t)(g + 8) * QDIM + col) =
            __floats2half2_rn(oa[ni][2] * inv1, oa[ni][3] * inv1);
    }
}

// ---------------------------------------------------------------------------
// Launch
// ---------------------------------------------------------------------------
extern "C" void kernel_launch(void* const* d_in, const int* in_sizes, int n_in,
                              void* d_out, int out_size)
{
    const float* query = (const float*)d_in[0];
    const float* key   = (const float*)d_in[1];
    const float* value = (const float*)d_in[2];
    const float* Wq = (const float*)d_in[5];
    const float* Wk = (const float*)d_in[6];
    const float* Wv = (const float*)d_in[7];
    const float* Wo = (const float*)d_in[8];
    float* out = (float*)d_out;

    float *pQ, *pK, *pV;
    __half *pAh, *pQh, *pKh, *pVh, *pAOh, *pWqTh, *pWkTh, *pWvTh, *pWoTh;
    cudaGetSymbolAddress((void**)&pQ,    g_Q);
    cudaGetSymbolAddress((void**)&pK,    g_K);
    cudaGetSymbolAddress((void**)&pV,    g_V);
    cudaGetSymbolAddress((void**)&pAh,   g_Ah);
    cudaGetSymbolAddress((void**)&pQh,   g_Qh);
    cudaGetSymbolAddress((void**)&pKh,   g_Kh);
    cudaGetSymbolAddress((void**)&pVh,   g_Vh);
    cudaGetSymbolAddress((void**)&pAOh,  g_AOh);
    cudaGetSymbolAddress((void**)&pWqTh, g_WqTh);
    cudaGetSymbolAddress((void**)&pWkTh, g_WkTh);
    cudaGetSymbolAddress((void**)&pWvTh, g_WvTh);
    cudaGetSymbolAddress((void**)&pWoTh, g_WoTh);

    cudaFuncSetAttribute(gemm_f16, cudaFuncAttributeMaxDynamicSharedMemorySize, GEMM16_SMEM);
    cudaFuncSetAttribute(flash2,   cudaFuncAttributeMaxDynamicSharedMemorySize, FL2_SMEM);

    dim3 tb(32, 8);
    transpose_h<<<dim3(QDIM  / 32, EMB / 32), tb>>>(Wq, pWqTh, EMB, QDIM);
    transpose_h<<<dim3(KVDIM / 32, EMB / 32), tb>>>(Wk, pWkTh, EMB, KVDIM);
    transpose_h<<<dim3(KVDIM / 32, EMB / 32), tb>>>(Wv, pWvTh, EMB, KVDIM);
    transpose_h<<<dim3(EMB   / 32, QDIM / 32), tb>>>(Wo, pWoTh, QDIM, EMB);

    const int nact = MROWS * EMB;
    // Q projection
    conv_f2h<<<nact / 1024, 256>>>(query, pAh, nact);
    gemm_f16<<<dim3(QDIM / 128, MROWS / 128), 256, GEMM16_SMEM>>>(pAh, pWqTh, pQ, MROWS, QDIM, EMB);
    // K projection
    conv_f2h<<<nact / 1024, 256>>>(key, pAh, nact);
    gemm_f16<<<dim3(KVDIM / 128, MROWS / 128), 256, GEMM16_SMEM>>>(pAh, pWkTh, pK, MROWS, KVDIM, EMB);
    // V projection
    conv_f2h<<<nact / 1024, 256>>>(value, pAh, nact);
    gemm_f16<<<dim3(KVDIM / 128, MROWS / 128), 256, GEMM16_SMEM>>>(pAh, pWvTh, pV, MROWS, KVDIM, EMB);

    // RoPE (+ fold softmax scale*log2e into Q) and V convert
    int totq = MROWS * NH * 64;
    rope_h<<<(totq + 255) / 256, 256>>>(pQ, pQh, NH, QSCALE, totq);
    int totk = MROWS * NKVH * 64;
    rope_h<<<(totk + 255) / 256, 256>>>(pK, pKh, NKVH, 1.0f, totk);
    int nv = MROWS * KVDIM;
    conv_f2h<<<nv / 1024, 256>>>(pV, pVh, nv);

    // Attention
    flash2<<<dim3(SEQ / 128, NH, BSZ), 256, FL2_SMEM>>>(pQh, pKh, pVh, pAOh);

    // Output projection
    gemm_f16<<<dim3(EMB / 128, MROWS / 128), 256, GEMM16_SMEM>>>(pAOh, pWoTh, out, MROWS, EMB, QDIM);
}

// round 5
// speedup vs baseline: 8.2216x; 1.1666x over previous
#include <cuda_runtime.h>
#include <cuda_fp16.h>
#include <math.h>
#include <stdint.h>

#define BSZ   2
#define SEQ   2048
#define EMB   4096
#define NH    32
#define NKVH  8
#define HD    128
#define GROUPS (NH / NKVH)
#define MROWS (BSZ * SEQ)          // 4096
#define QDIM  (NH * HD)            // 4096
#define KVDIM (NKVH * HD)          // 1024

// log2(e)/sqrt(128), folded into Q so softmax uses bare exp2
#define QSCALE 0.12751744f

// Scratch (device globals)
__device__ float  g_Q [(size_t)MROWS * QDIM];
__device__ float  g_K [(size_t)MROWS * KVDIM];
__device__ float  g_V [(size_t)MROWS * KVDIM];
__device__ __half g_Ah [(size_t)MROWS * EMB];
__device__ __half g_Qh [(size_t)MROWS * QDIM];
__device__ __half g_Kh [(size_t)MROWS * KVDIM];
__device__ __half g_Vh [(size_t)MROWS * KVDIM];
__device__ __half g_AOh[(size_t)MROWS * QDIM];
__device__ __half g_WqTh[(size_t)QDIM * EMB];
__device__ __half g_WkTh[(size_t)KVDIM * EMB];
__device__ __half g_WvTh[(size_t)KVDIM * EMB];
__device__ __half g_WoTh[(size_t)EMB * QDIM];

// ---------------------------------------------------------------------------
// Helpers
// ---------------------------------------------------------------------------
__device__ __forceinline__ uint32_t smem_u32(const void* p) {
    uint32_t a;
    asm("{ .reg .u64 t; cvta.to.shared.u64 t, %1; cvt.u32.u64 %0, t; }" : "=r"(a) : "l"(p));
    return a;
}
__device__ __forceinline__ void cpasync16(uint32_t dst, const void* src) {
    asm volatile("cp.async.cg.shared.global [%0], [%1], 16;" :: "r"(dst), "l"(src) : "memory");
}
#define CP_COMMIT() asm volatile("cp.async.commit_group;" ::: "memory")
#define CP_WAIT(n)  asm volatile("cp.async.wait_group %0;" :: "n"(n) : "memory")

__device__ __forceinline__ void mma_f16(float* d, const uint32_t* a, uint32_t b0, uint32_t b1) {
    asm volatile("mma.sync.aligned.m16n8k16.row.col.f32.f16.f16.f32 "
        "{%0,%1,%2,%3}, {%4,%5,%6,%7}, {%8,%9}, {%0,%1,%2,%3};"
        : "+f"(d[0]), "+f"(d[1]), "+f"(d[2]), "+f"(d[3])
        : "r"(a[0]), "r"(a[1]), "r"(a[2]), "r"(a[3]), "r"(b0), "r"(b1));
}
__device__ __forceinline__ void ldsm4(uint32_t& r0, uint32_t& r1, uint32_t& r2, uint32_t& r3,
                                      uint32_t addr) {
    asm volatile("ldmatrix.sync.aligned.m8n8.x4.shared.b16 {%0,%1,%2,%3}, [%4];"
        : "=r"(r0), "=r"(r1), "=r"(r2), "=r"(r3) : "r"(addr));
}
__device__ __forceinline__ void ldsm4t(uint32_t& r0, uint32_t& r1, uint32_t& r2, uint32_t& r3,
                                       uint32_t addr) {
    asm volatile("ldmatrix.sync.aligned.m8n8.x4.trans.shared.b16 {%0,%1,%2,%3}, [%4];"
        : "=r"(r0), "=r"(r1), "=r"(r2), "=r"(r3) : "r"(addr));
}

// ---------------------------------------------------------------------------
// Transpose + fp32->half: out[c][r] = (half)in[r][c]; in is R x C.
// ---------------------------------------------------------------------------
__global__ void transpose_h(const float* __restrict__ in, __half* __restrict__ out,
                            int R, int C)
{
    __shared__ float t[32][33];
    int bc = blockIdx.x * 32, br = blockIdx.y * 32;
    int x = threadIdx.x, y = threadIdx.y;
#pragma unroll
    for (int j = 0; j < 32; j += 8)
        t[y + j][x] = in[(size_t)(br + y + j) * C + bc + x];
    __syncthreads();
#pragma unroll
    for (int j = 0; j < 32; j += 8)
        out[(size_t)(bc + y + j) * R + br + x] = __float2half(t[x][y + j]);
}

__global__ void conv_f2h(const float* __restrict__ in, __half* __restrict__ out, int n)
{
    int i = (blockIdx.x * blockDim.x + threadIdx.x) * 4;
    if (i >= n) return;
    float4 v = *(const float4*)(in + i);
    *(__half2*)(out + i)     = __floats2half2_rn(v.x, v.y);
    *(__half2*)(out + i + 2) = __floats2half2_rn(v.z, v.w);
}

// ---------------------------------------------------------------------------
// fp16 tensor-core GEMM: C[M,N] = A[M,K] @ BT[N,K]^T
// 128x128 CTA tile, BK=64, 8 warps (64x32 warp tile), cp.async 3-stage,
// ldmatrix fragment loads. smem pitch 72 halves (144B).
// ---------------------------------------------------------------------------
#define HP 72
#define STG_HALF (2 * 128 * HP)                 // A+B halves per stage
#define STG_BYTES (STG_HALF * 2)                // 36864
#define GEMM16_SMEM (3 * STG_BYTES)             // 110592

__global__ __launch_bounds__(256, 2) void gemm_f16(const __half* __restrict__ A,
                                                   const __half* __restrict__ BT,
                                                   float* __restrict__ C,
                                                   int M, int N, int K)
{
    extern __shared__ __half smh[];
    const uint32_t sb = smem_u32(smh);

    const int tid  = threadIdx.x;
    const int wid  = tid >> 5, lane = tid & 31;
    const int g    = lane >> 2, tig = lane & 3;
    const int wm   = (wid >> 2) * 64;
    const int wn   = (wid & 3) * 32;
    const int bm   = blockIdx.y * 128, bn = blockIdx.x * 128;

    const __half* Ab0 = A  + (size_t)bm * K;
    const __half* Bb0 = BT + (size_t)bn * K;

    auto load_tile = [&](int c, int s) {
        const __half* Ab = Ab0 + c * 64;
        const __half* Bb = Bb0 + c * 64;
        uint32_t sa  = sb + (uint32_t)s * STG_BYTES;
        uint32_t sbb = sa + 128 * HP * 2;
#pragma unroll
        for (int l = 0; l < 4; l++) {
            int id = l * 256 + tid;
            int r = id >> 3, c8 = (id & 7) * 8;
            cpasync16(sa  + (uint32_t)(r * HP + c8) * 2, Ab + (size_t)r * K + c8);
            cpasync16(sbb + (uint32_t)(r * HP + c8) * 2, Bb + (size_t)r * K + c8);
        }
        CP_COMMIT();
    };

    // ldmatrix lane addressing (precompute per-thread row/col components)
    const int l7  = lane & 7;
    const int lb3 = (lane >> 3) & 1;
    const int lb4 = lane >> 4;

    float acc[4][4][4];
#pragma unroll
    for (int mi = 0; mi < 4; mi++)
#pragma unroll
        for (int ni = 0; ni < 4; ni++)
#pragma unroll
            for (int r = 0; r < 4; r++) acc[mi][ni][r] = 0.0f;

    const int iters = K / 64;
    load_tile(0, 0);
    if (iters > 1) load_tile(1, 1);

    for (int c = 0; c < iters; c++) {
        const int s = c % 3;
        if (c + 2 < iters) { load_tile(c + 2, (c + 2) % 3); CP_WAIT(2); }
        else if (c + 1 < iters) { CP_WAIT(1); }
        else { CP_WAIT(0); }
        __syncthreads();

        const uint32_t sA = sb + (uint32_t)s * STG_BYTES;
        const uint32_t sB = sA + 128 * HP * 2;

#pragma unroll
        for (int ks = 0; ks < 4; ks++) {
            const int kb = ks * 16;
            uint32_t af[4][4], bf[4][2];
#pragma unroll
            for (int mi = 0; mi < 4; mi++) {
                uint32_t addr = sA + (uint32_t)((wm + mi * 16 + l7 + lb3 * 8) * HP
                                                + kb + lb4 * 8) * 2;
                ldsm4(af[mi][0], af[mi][1], af[mi][2], af[mi][3], addr);
            }
#pragma unroll
            for (int nip = 0; nip < 2; nip++) {
                uint32_t addr = sB + (uint32_t)((wn + nip * 16 + l7 + lb4 * 8) * HP
                                                + kb + lb3 * 8) * 2;
                ldsm4(bf[nip*2][0], bf[nip*2][1], bf[nip*2+1][0], bf[nip*2+1][1], addr);
            }
#pragma unroll
            for (int mi = 0; mi < 4; mi++)
#pragma unroll
                for (int ni = 0; ni < 4; ni++)
                    mma_f16(acc[mi][ni], af[mi], bf[ni][0], bf[ni][1]);
        }
        __syncthreads();
    }

#pragma unroll
    for (int mi = 0; mi < 4; mi++) {
        int row0 = bm + wm + mi * 16 + g;
#pragma unroll
        for (int ni = 0; ni < 4; ni++) {
            int col = bn + wn + ni * 8 + tig * 2;
            *(float2*)(C + (size_t)row0 * N + col)       = make_float2(acc[mi][ni][0], acc[mi][ni][1]);
            *(float2*)(C + (size_t)(row0 + 8) * N + col) = make_float2(acc[mi][ni][2], acc[mi][ni][3]);
        }
    }
}

// ---------------------------------------------------------------------------
// RoPE fp32 -> half with pre-scale. position = row % SEQ.
// ---------------------------------------------------------------------------
__global__ void rope_h(const float* __restrict__ X, __half* __restrict__ Y,
                       int nheads, float sc, int total)
{
    int idx = blockIdx.x * blockDim.x + threadIdx.x;
    if (idx >= total) return;
    int d   = idx & 63;
    int h   = (idx >> 6) % nheads;
    int row = idx / (64 * nheads);
    float p   = (float)(row % SEQ);
    float inv = powf(10000.0f, -(float)(2 * d) / 128.0f);
    float ang = p * inv;
    float s, c;
    sincosf(ang, &s, &c);
    size_t base = (size_t)row * ((size_t)nheads * HD) + (size_t)h * HD + d;
    float x1 = X[base];
    float x2 = X[base + 64];
    Y[base]      = __float2half((x1 * c - x2 * s) * sc);
    Y[base + 64] = __float2half((x2 * c + x1 * s) * sc);
}

// ---------------------------------------------------------------------------
// Flash attention v3 (fp16 MMA, ldmatrix, cp.async double-buffered K/V).
// Q tile 128, K tile 64. 8 warps; warp owns 16 q-rows.
// smem: Qs[128][136], Ks[2][64][136], Vs[2][64][136] (row-major), Ps[128][72]
// ---------------------------------------------------------------------------
#define QP 136
#define VP 72
#define KVST (64 * QP)                          // halves per K/V stage
#define FL3_SMEM ((128*QP + 4*KVST + 128*VP) * 2)   // 122880 bytes

__global__ __launch_bounds__(256, 1) void flash3(const __half* __restrict__ Q,
                                                 const __half* __restrict__ K,
                                                 const __half* __restrict__ V,
                                                 __half* __restrict__ O)
{
    extern __shared__ __half hs[];
    __half* Qs  = hs;                        // [128][136]
    __half* Ks0 = Qs + 128 * QP;             // [2][64][136]
    __half* Vs0 = Ks0 + 2 * KVST;            // [2][64][136]
    __half* Ps  = Vs0 + 2 * KVST;            // [128][72]

    const uint32_t sbQ = smem_u32(Qs);
    const uint32_t sbK = smem_u32(Ks0);
    const uint32_t sbV = smem_u32(Vs0);
    const uint32_t sbP = smem_u32(Ps);
    __half2* P2 = (__half2*)Ps;

    const int qi  = blockIdx.x;              // 0..15
    const int h   = blockIdx.y;
    const int b   = blockIdx.z;
    const int kvh = h / GROUPS;
    const int tid = threadIdx.x;
    const int wid = tid >> 5, lane = tid & 31;
    const int g   = lane >> 2, tig = lane & 3;
    const int wq  = wid * 16;
    const int l7  = lane & 7;
    const int lb3 = (lane >> 3) & 1;
    const int lb4 = lane >> 4;

    const __half* Qg = Q + (size_t)(b * SEQ + qi * 128) * QDIM + h * HD;
    const __half* Kg = K + (size_t)(b * SEQ) * KVDIM + kvh * HD;
    const __half* Vg = V + (size_t)(b * SEQ) * KVDIM + kvh * HD;

    // K and V tiles: 64 rows x 128 halves each -> 8 cp.async per thread
    auto load_kv = [&](int kb, int s) {
        const __half* Kt = Kg + (size_t)(kb * 64) * KVDIM;
        const __half* Vt = Vg + (size_t)(kb * 64) * KVDIM;
        uint32_t ks_ = sbK + (uint32_t)s * (KVST * 2);
        uint32_t vs_ = sbV + (uint32_t)s * (KVST * 2);
#pragma unroll
        for (int l = 0; l < 4; l++) {
            int id = l * 256 + tid;
            int r = id >> 4, c8 = (id & 15) * 8;
            cpasync16(ks_ + (uint32_t)(r * QP + c8) * 2, Kt + (size_t)r * KVDIM + c8);
            cpasync16(vs_ + (uint32_t)(r * QP + c8) * 2, Vt + (size_t)r * KVDIM + c8);
        }
        CP_COMMIT();
    };

    // load Q tile (plain)
#pragma unroll
    for (int l = 0; l < 8; l++) {
        int id = l * 256 + tid;
        int r = id >> 4, c8 = (id & 15) * 8;
        *(uint4*)(Qs + r * QP + c8) = *(const uint4*)(Qg + (size_t)r * QDIM + c8);
    }

    float m0 = -INFINITY, m1 = -INFINITY, l0 = 0.f, l1 = 0.f;
    float oa[16][4];
#pragma unroll
    for (int ni = 0; ni < 16; ni++)
#pragma unroll
        for (int r = 0; r < 4; r++) oa[ni][r] = 0.f;

    const int kmax = 2 * qi + 2;
    load_kv(0, 0);

    for (int kb = 0; kb < kmax; kb++) {
        const int s = kb & 1;
        if (kb + 1 < kmax) { load_kv(kb + 1, s ^ 1); CP_WAIT(1); }
        else               { CP_WAIT(0); }
        __syncthreads();

        const uint32_t sK = sbK + (uint32_t)s * (KVST * 2);
        const uint32_t sV = sbV + (uint32_t)s * (KVST * 2);

        // ---- S = Q K^T (warp: 16 x 64) ----
        float sa[8][4];
#pragma unroll
        for (int ni = 0; ni < 8; ni++)
#pragma unroll
            for (int r = 0; r < 4; r++) sa[ni][r] = 0.f;

#pragma unroll
        for (int ks = 0; ks < 8; ks++) {
            const int kc = ks * 16;
            uint32_t a[4], bf[8][2];
            {
                uint32_t addr = sbQ + (uint32_t)((wq + l7 + lb3 * 8) * QP + kc + lb4 * 8) * 2;
                ldsm4(a[0], a[1], a[2], a[3], addr);
            }
#pragma unroll
            for (int nip = 0; nip < 4; nip++) {
                uint32_t addr = sK + (uint32_t)((nip * 16 + l7 + lb4 * 8) * QP + kc + lb3 * 8) * 2;
                ldsm4(bf[nip*2][0], bf[nip*2][1], bf[nip*2+1][0], bf[nip*2+1][1], addr);
            }
#pragma unroll
            for (int ni = 0; ni < 8; ni++)
                mma_f16(sa[ni], a, bf[ni][0], bf[ni][1]);
        }

        // ---- causal mask (diagonal tiles only) ----
        if (kb >= 2 * qi) {
            int r0 = qi * 128 + wq + g;
#pragma unroll
            for (int ni = 0; ni < 8; ni++) {
                int c0 = kb * 64 + ni * 8 + 2 * tig;
                if (c0 > r0)         sa[ni][0] = -INFINITY;
                if (c0 + 1 > r0)     sa[ni][1] = -INFINITY;
                if (c0 > r0 + 8)     sa[ni][2] = -INFINITY;
                if (c0 + 1 > r0 + 8) sa[ni][3] = -INFINITY;
            }
        }

        // ---- online softmax ----
        float mx0 = -INFINITY, mx1 = -INFINITY;
#pragma unroll
        for (int ni = 0; ni < 8; ni++) {
            mx0 = fmaxf(mx0, fmaxf(sa[ni][0], sa[ni][1]));
            mx1 = fmaxf(mx1, fmaxf(sa[ni][2], sa[ni][3]));
        }
        mx0 = fmaxf(mx0, __shfl_xor_sync(0xffffffffu, mx0, 1));
        mx0 = fmaxf(mx0, __shfl_xor_sync(0xffffffffu, mx0, 2));
        mx1 = fmaxf(mx1, __shfl_xor_sync(0xffffffffu, mx1, 1));
        mx1 = fmaxf(mx1, __shfl_xor_sync(0xffffffffu, mx1, 2));

        float mm0 = fmaxf(m0, mx0), mm1 = fmaxf(m1, mx1);
        float sub0 = (mm0 == -INFINITY) ? 0.f : mm0;
        float sub1 = (mm1 == -INFINITY) ? 0.f : mm1;
        float al0 = exp2f(m0 - sub0);
        float al1 = exp2f(m1 - sub1);
        m0 = mm0; m1 = mm1;

        float ls0 = 0.f, ls1 = 0.f;
#pragma unroll
        for (int ni = 0; ni < 8; ni++) {
            float p0 = exp2f(sa[ni][0] - sub0);
            float p1 = exp2f(sa[ni][1] - sub0);
            float p2 = exp2f(sa[ni][2] - sub1);
            float p3 = exp2f(sa[ni][3] - sub1);
            ls0 += p0 + p1; ls1 += p2 + p3;
            P2[(wq + g) * (VP/2) + ni * 4 + tig]     = __floats2half2_rn(p0, p1);
            P2[(wq + g + 8) * (VP/2) + ni * 4 + tig] = __floats2half2_rn(p2, p3);
        }
        ls0 += __shfl_xor_sync(0xffffffffu, ls0, 1);
        ls0 += __shfl_xor_sync(0xffffffffu, ls0, 2);
        ls1 += __shfl_xor_sync(0xffffffffu, ls1, 1);
        ls1 += __shfl_xor_sync(0xffffffffu, ls1, 2);
        l0 = l0 * al0 + ls0;
        l1 = l1 * al1 + ls1;

#pragma unroll
        for (int ni = 0; ni < 16; ni++) {
            oa[ni][0] *= al0; oa[ni][1] *= al0;
            oa[ni][2] *= al1; oa[ni][3] *= al1;
        }
        __syncwarp();   // Ps visibility within warp

        // ---- O += P @ V (A=Ps rows of warp; B=V via ldmatrix.trans) ----
#pragma unroll
        for (int ks = 0; ks < 4; ks++) {
            const int kc = ks * 16;
            uint32_t a[4];
            {
                uint32_t addr = sbP + (uint32_t)((wq + l7 + lb3 * 8) * VP + kc + lb4 * 8) * 2;
                ldsm4(a[0], a[1], a[2], a[3], addr);
            }
#pragma unroll
            for (int nip = 0; nip < 8; nip++) {
                uint32_t bf0, bf1, bf2, bf3;
                uint32_t addr = sV + (uint32_t)((kc + l7 + lb3 * 8) * QP + nip * 16 + lb4 * 8) * 2;
                ldsm4t(bf0, bf1, bf2, bf3, addr);
                mma_f16(oa[nip*2],     a, bf0, bf1);
                mma_f16(oa[nip*2 + 1], a, bf2, bf3);
            }
        }
        __syncthreads();  // stage reuse barrier
    }

    // ---- epilogue ----
    float inv0 = 1.0f / l0, inv1 = 1.0f / l1;
    __half* Og = O + (size_t)(b * SEQ + qi * 128 + wq) * QDIM + h * HD;
#pragma unroll
    for (int ni = 0; ni < 16; ni++) {
        int col = ni * 8 + 2 * tig;
        *(__half2*)(Og + (size_t)g * QDIM + col) =
            __floats2half2_rn(oa[ni][0] * inv0, oa[ni][1] * inv0);
        *(__half2*)(Og + (size_t)(g + 8) * QDIM + col) =
            __floats2half2_rn(oa[ni][2] * inv1, oa[ni][3] * inv1);
    }
}

// ---------------------------------------------------------------------------
// Launch
// ---------------------------------------------------------------------------
extern "C" void kernel_launch(void* const* d_in, const int* in_sizes, int n_in,
                              void* d_out, int out_size)
{
    const float* query = (const float*)d_in[0];
    const float* key   = (const float*)d_in[1];
    const float* value = (const float*)d_in[2];
    const float* Wq = (const float*)d_in[5];
    const float* Wk = (const float*)d_in[6];
    const float* Wv = (const float*)d_in[7];
    const float* Wo = (const float*)d_in[8];
    float* out = (float*)d_out;

    float *pQ, *pK, *pV;
    __half *pAh, *pQh, *pKh, *pVh, *pAOh, *pWqTh, *pWkTh, *pWvTh, *pWoTh;
    cudaGetSymbolAddress((void**)&pQ,    g_Q);
    cudaGetSymbolAddress((void**)&pK,    g_K);
    cudaGetSymbolAddress((void**)&pV,    g_V);
    cudaGetSymbolAddress((void**)&pAh,   g_Ah);
    cudaGetSymbolAddress((void**)&pQh,   g_Qh);
    cudaGetSymbolAddress((void**)&pKh,   g_Kh);
    cudaGetSymbolAddress((void**)&pVh,   g_Vh);
    cudaGetSymbolAddress((void**)&pAOh,  g_AOh);
    cudaGetSymbolAddress((void**)&pWqTh, g_WqTh);
    cudaGetSymbolAddress((void**)&pWkTh, g_WkTh);
    cudaGetSymbolAddress((void**)&pWvTh, g_WvTh);
    cudaGetSymbolAddress((void**)&pWoTh, g_WoTh);

    cudaFuncSetAttribute(gemm_f16, cudaFuncAttributeMaxDynamicSharedMemorySize, GEMM16_SMEM);
    cudaFuncSetAttribute(flash3,   cudaFuncAttributeMaxDynamicSharedMemorySize, FL3_SMEM);

    dim3 tb(32, 8);
    transpose_h<<<dim3(QDIM  / 32, EMB / 32), tb>>>(Wq, pWqTh, EMB, QDIM);
    transpose_h<<<dim3(KVDIM / 32, EMB / 32), tb>>>(Wk, pWkTh, EMB, KVDIM);
    transpose_h<<<dim3(KVDIM / 32, EMB / 32), tb>>>(Wv, pWvTh, EMB, KVDIM);
    transpose_h<<<dim3(EMB   / 32, QDIM / 32), tb>>>(Wo, pWoTh, QDIM, EMB);

    const int nact = MROWS * EMB;
    conv_f2h<<<nact / 1024, 256>>>(query, pAh, nact);
    gemm_f16<<<dim3(QDIM / 128, MROWS / 128), 256, GEMM16_SMEM>>>(pAh, pWqTh, pQ, MROWS, QDIM, EMB);
    conv_f2h<<<nact / 1024, 256>>>(key, pAh, nact);
    gemm_f16<<<dim3(KVDIM / 128, MROWS / 128), 256, GEMM16_SMEM>>>(pAh, pWkTh, pK, MROWS, KVDIM, EMB);
    conv_f2h<<<nact / 1024, 256>>>(value, pAh, nact);
    gemm_f16<<<dim3(KVDIM / 128, MROWS / 128), 256, GEMM16_SMEM>>>(pAh, pWvTh, pV, MROWS, KVDIM, EMB);

    int totq = MROWS * NH * 64;
    rope_h<<<(totq + 255) / 256, 256>>>(pQ, pQh, NH, QSCALE, totq);
    int totk = MROWS * NKVH * 64;
    rope_h<<<(totk + 255) / 256, 256>>>(pK, pKh, NKVH, 1.0f, totk);
    int nv = MROWS * KVDIM;
    conv_f2h<<<nv / 1024, 256>>>(pV, pVh, nv);

    flash3<<<dim3(SEQ / 128, NH, BSZ), 256, FL3_SMEM>>>(pQh, pKh, pVh, pAOh);

    gemm_f16<<<dim3(EMB / 128, MROWS / 128), 256, GEMM16_SMEM>>>(pAOh, pWoTh, out, MROWS, EMB, QDIM);
}

// round 6
// speedup vs baseline: 8.5172x; 1.0360x over previous
#include <cuda_runtime.h>
#include <cuda_fp16.h>
#include <math.h>
#include <stdint.h>

#define BSZ   2
#define SEQ   2048
#define EMB   4096
#define NH    32
#define NKVH  8
#define HD    128
#define GROUPS (NH / NKVH)
#define MROWS (BSZ * SEQ)          // 4096
#define QDIM  (NH * HD)            // 4096
#define KVDIM (NKVH * HD)          // 1024

// log2(e)/sqrt(128), folded into Q so softmax uses bare exp2
#define QSCALE 0.12751744f

// Scratch (device globals)
__device__ float  g_Q [(size_t)MROWS * QDIM];
__device__ float  g_K [(size_t)MROWS * KVDIM];
__device__ __half g_Ah [(size_t)MROWS * EMB];
__device__ __half g_Qh [(size_t)MROWS * QDIM];
__device__ __half g_Kh [(size_t)MROWS * KVDIM];
__device__ __half g_Vh [(size_t)MROWS * KVDIM];
__device__ __half g_AOh[(size_t)MROWS * QDIM];
__device__ __half g_WqTh[(size_t)QDIM * EMB];
__device__ __half g_WkTh[(size_t)KVDIM * EMB];
__device__ __half g_WvTh[(size_t)KVDIM * EMB];
__device__ __half g_WoTh[(size_t)EMB * QDIM];

// ---------------------------------------------------------------------------
// Helpers
// ---------------------------------------------------------------------------
__device__ __forceinline__ uint32_t smem_u32(const void* p) {
    uint32_t a;
    asm("{ .reg .u64 t; cvta.to.shared.u64 t, %1; cvt.u32.u64 %0, t; }" : "=r"(a) : "l"(p));
    return a;
}
__device__ __forceinline__ void cpasync16(uint32_t dst, const void* src) {
    asm volatile("cp.async.cg.shared.global [%0], [%1], 16;" :: "r"(dst), "l"(src) : "memory");
}
#define CP_COMMIT() asm volatile("cp.async.commit_group;" ::: "memory")
#define CP_WAIT(n)  asm volatile("cp.async.wait_group %0;" :: "n"(n) : "memory")

__device__ __forceinline__ void mma_f16(float* d, const uint32_t* a, uint32_t b0, uint32_t b1) {
    asm volatile("mma.sync.aligned.m16n8k16.row.col.f32.f16.f16.f32 "
        "{%0,%1,%2,%3}, {%4,%5,%6,%7}, {%8,%9}, {%0,%1,%2,%3};"
        : "+f"(d[0]), "+f"(d[1]), "+f"(d[2]), "+f"(d[3])
        : "r"(a[0]), "r"(a[1]), "r"(a[2]), "r"(a[3]), "r"(b0), "r"(b1));
}
__device__ __forceinline__ void ldsm4(uint32_t& r0, uint32_t& r1, uint32_t& r2, uint32_t& r3,
                                      uint32_t addr) {
    asm volatile("ldmatrix.sync.aligned.m8n8.x4.shared.b16 {%0,%1,%2,%3}, [%4];"
        : "=r"(r0), "=r"(r1), "=r"(r2), "=r"(r3) : "r"(addr));
}
__device__ __forceinline__ void ldsm4t(uint32_t& r0, uint32_t& r1, uint32_t& r2, uint32_t& r3,
                                       uint32_t addr) {
    asm volatile("ldmatrix.sync.aligned.m8n8.x4.trans.shared.b16 {%0,%1,%2,%3}, [%4];"
        : "=r"(r0), "=r"(r1), "=r"(r2), "=r"(r3) : "r"(addr));
}

// ---------------------------------------------------------------------------
// Transpose + fp32->half: out[c][r] = (half)in[r][c]; in is R x C.
// ---------------------------------------------------------------------------
__global__ void transpose_h(const float* __restrict__ in, __half* __restrict__ out,
                            int R, int C)
{
    __shared__ float t[32][33];
    int bc = blockIdx.x * 32, br = blockIdx.y * 32;
    int x = threadIdx.x, y = threadIdx.y;
#pragma unroll
    for (int j = 0; j < 32; j += 8)
        t[y + j][x] = in[(size_t)(br + y + j) * C + bc + x];
    __syncthreads();
#pragma unroll
    for (int j = 0; j < 32; j += 8)
        out[(size_t)(bc + y + j) * R + br + x] = __float2half(t[x][y + j]);
}

__global__ void conv_f2h(const float* __restrict__ in, __half* __restrict__ out, int n)
{
    int i = (blockIdx.x * blockDim.x + threadIdx.x) * 4;
    if (i >= n) return;
    float4 v = *(const float4*)(in + i);
    *(__half2*)(out + i)     = __floats2half2_rn(v.x, v.y);
    *(__half2*)(out + i + 2) = __floats2half2_rn(v.z, v.w);
}

// ---------------------------------------------------------------------------
// fp16 tensor-core GEMM: C[M,N] = A[M,K] @ BT[N,K]^T
// 128x128 CTA tile, BK=64, 8 warps (64x32), cp.async 3-stage,
// ldmatrix frags, ONE barrier per k-iteration (load issued post-barrier).
// ---------------------------------------------------------------------------
#define HP 72
#define STG_HALF (2 * 128 * HP)
#define STG_BYTES (STG_HALF * 2)                // 36864
#define GEMM16_SMEM (3 * STG_BYTES)             // 110592

template <bool OUT_HALF>
__global__ __launch_bounds__(256, 2) void gemm_f16(const __half* __restrict__ A,
                                                   const __half* __restrict__ BT,
                                                   void* __restrict__ Cv,
                                                   int M, int N, int K)
{
    extern __shared__ __half smh[];
    const uint32_t sb = smem_u32(smh);

    const int tid  = threadIdx.x;
    const int wid  = tid >> 5, lane = tid & 31;
    const int g    = lane >> 2, tig = lane & 3;
    const int wm   = (wid >> 2) * 64;
    const int wn   = (wid & 3) * 32;
    const int bm   = blockIdx.y * 128, bn = blockIdx.x * 128;

    const __half* Ab0 = A  + (size_t)bm * K;
    const __half* Bb0 = BT + (size_t)bn * K;

    auto load_tile = [&](int c, int s) {
        const __half* Ab = Ab0 + c * 64;
        const __half* Bb = Bb0 + c * 64;
        uint32_t sa  = sb + (uint32_t)s * STG_BYTES;
        uint32_t sbb = sa + 128 * HP * 2;
#pragma unroll
        for (int l = 0; l < 4; l++) {
            int id = l * 256 + tid;
            int r = id >> 3, c8 = (id & 7) * 8;
            cpasync16(sa  + (uint32_t)(r * HP + c8) * 2, Ab + (size_t)r * K + c8);
            cpasync16(sbb + (uint32_t)(r * HP + c8) * 2, Bb + (size_t)r * K + c8);
        }
        CP_COMMIT();
    };

    const int l7  = lane & 7;
    const int lb3 = (lane >> 3) & 1;
    const int lb4 = lane >> 4;

    float acc[4][4][4];
#pragma unroll
    for (int mi = 0; mi < 4; mi++)
#pragma unroll
        for (int ni = 0; ni < 4; ni++)
#pragma unroll
            for (int r = 0; r < 4; r++) acc[mi][ni][r] = 0.0f;

    const int iters = K / 64;
    load_tile(0, 0);
    load_tile(1, 1);

    for (int c = 0; c < iters; c++) {
        const int s = c % 3;
        if (c + 1 < iters) { CP_WAIT(1); } else { CP_WAIT(0); }
        __syncthreads();
        if (c + 2 < iters) load_tile(c + 2, (c + 2) % 3);

        const uint32_t sA = sb + (uint32_t)s * STG_BYTES;
        const uint32_t sB = sA + 128 * HP * 2;

#pragma unroll
        for (int ks = 0; ks < 4; ks++) {
            const int kb = ks * 16;
            uint32_t af[4][4], bf[4][2];
#pragma unroll
            for (int mi = 0; mi < 4; mi++) {
                uint32_t addr = sA + (uint32_t)((wm + mi * 16 + l7 + lb3 * 8) * HP
                                                + kb + lb4 * 8) * 2;
                ldsm4(af[mi][0], af[mi][1], af[mi][2], af[mi][3], addr);
            }
#pragma unroll
            for (int nip = 0; nip < 2; nip++) {
                uint32_t addr = sB + (uint32_t)((wn + nip * 16 + l7 + lb4 * 8) * HP
                                                + kb + lb3 * 8) * 2;
                ldsm4(bf[nip*2][0], bf[nip*2][1], bf[nip*2+1][0], bf[nip*2+1][1], addr);
            }
#pragma unroll
            for (int mi = 0; mi < 4; mi++)
#pragma unroll
                for (int ni = 0; ni < 4; ni++)
                    mma_f16(acc[mi][ni], af[mi], bf[ni][0], bf[ni][1]);
        }
    }

#pragma unroll
    for (int mi = 0; mi < 4; mi++) {
        int row0 = bm + wm + mi * 16 + g;
#pragma unroll
        for (int ni = 0; ni < 4; ni++) {
            int col = bn + wn + ni * 8 + tig * 2;
            if (OUT_HALF) {
                __half* C = (__half*)Cv;
                *(__half2*)(C + (size_t)row0 * N + col) =
                    __floats2half2_rn(acc[mi][ni][0], acc[mi][ni][1]);
                *(__half2*)(C + (size_t)(row0 + 8) * N + col) =
                    __floats2half2_rn(acc[mi][ni][2], acc[mi][ni][3]);
            } else {
                float* C = (float*)Cv;
                *(float2*)(C + (size_t)row0 * N + col)       = make_float2(acc[mi][ni][0], acc[mi][ni][1]);
                *(float2*)(C + (size_t)(row0 + 8) * N + col) = make_float2(acc[mi][ni][2], acc[mi][ni][3]);
            }
        }
    }
}

// ---------------------------------------------------------------------------
// RoPE fp32 -> half with pre-scale. position = row % SEQ.
// ---------------------------------------------------------------------------
__global__ void rope_h(const float* __restrict__ X, __half* __restrict__ Y,
                       int nheads, float sc, int total)
{
    int idx = blockIdx.x * blockDim.x + threadIdx.x;
    if (idx >= total) return;
    int d   = idx & 63;
    int h   = (idx >> 6) % nheads;
    int row = idx / (64 * nheads);
    float p   = (float)(row % SEQ);
    float inv = powf(10000.0f, -(float)(2 * d) / 128.0f);
    float ang = p * inv;
    float s, c;
    sincosf(ang, &s, &c);
    size_t base = (size_t)row * ((size_t)nheads * HD) + (size_t)h * HD + d;
    float x1 = X[base];
    float x2 = X[base + 64];
    Y[base]      = __float2half((x1 * c - x2 * s) * sc);
    Y[base + 64] = __float2half((x2 * c + x1 * s) * sc);
}

// ---------------------------------------------------------------------------
// Flash attention v4: fp16 MMA, ldmatrix, 3-stage cp.async K/V pipeline,
// ONE barrier per kv-iteration. Q tile 128, K tile 64, 8 warps.
// smem: Qs[128][136], K/V stages 3x([64][136]+[64][136]), Ps[128][72]
// ---------------------------------------------------------------------------
#define QP 136
#define VP 72
#define KVST (2 * 64 * QP)                      // halves per stage (K+V)
#define FL4_SMEM ((128*QP + 3*KVST + 128*VP) * 2)   // 157696 bytes

__global__ __launch_bounds__(256, 1) void flash4(const __half* __restrict__ Q,
                                                 const __half* __restrict__ K,
                                                 const __half* __restrict__ V,
                                                 __half* __restrict__ O)
{
    extern __shared__ __half hs[];
    __half* Qs  = hs;                        // [128][136]
    __half* KV0 = Qs + 128 * QP;             // 3 stages: K[64][136] then V[64][136]
    __half* Ps  = KV0 + 3 * KVST;            // [128][72]

    const uint32_t sbQ  = smem_u32(Qs);
    const uint32_t sbKV = smem_u32(KV0);
    const uint32_t sbP  = smem_u32(Ps);
    __half2* P2 = (__half2*)Ps;

    const int qi  = (int)gridDim.x - 1 - (int)blockIdx.x;   // big tiles first
    const int h   = blockIdx.y;
    const int b   = blockIdx.z;
    const int kvh = h / GROUPS;
    const int tid = threadIdx.x;
    const int wid = tid >> 5, lane = tid & 31;
    const int g   = lane >> 2, tig = lane & 3;
    const int wq  = wid * 16;
    const int l7  = lane & 7;
    const int lb3 = (lane >> 3) & 1;
    const int lb4 = lane >> 4;

    const __half* Qg = Q + (size_t)(b * SEQ + qi * 128) * QDIM + h * HD;
    const __half* Kg = K + (size_t)(b * SEQ) * KVDIM + kvh * HD;
    const __half* Vg = V + (size_t)(b * SEQ) * KVDIM + kvh * HD;

    auto load_kv = [&](int kb, int s) {
        const __half* Kt = Kg + (size_t)(kb * 64) * KVDIM;
        const __half* Vt = Vg + (size_t)(kb * 64) * KVDIM;
        uint32_t ks_ = sbKV + (uint32_t)s * (KVST * 2);
        uint32_t vs_ = ks_ + 64 * QP * 2;
#pragma unroll
        for (int l = 0; l < 4; l++) {
            int id = l * 256 + tid;
            int r = id >> 4, c8 = (id & 15) * 8;
            cpasync16(ks_ + (uint32_t)(r * QP + c8) * 2, Kt + (size_t)r * KVDIM + c8);
            cpasync16(vs_ + (uint32_t)(r * QP + c8) * 2, Vt + (size_t)r * KVDIM + c8);
        }
        CP_COMMIT();
    };

    // load Q tile
#pragma unroll
    for (int l = 0; l < 8; l++) {
        int id = l * 256 + tid;
        int r = id >> 4, c8 = (id & 15) * 8;
        *(uint4*)(Qs + r * QP + c8) = *(const uint4*)(Qg + (size_t)r * QDIM + c8);
    }

    float m0 = -INFINITY, m1 = -INFINITY, l0 = 0.f, l1 = 0.f;
    float oa[16][4];
#pragma unroll
    for (int ni = 0; ni < 16; ni++)
#pragma unroll
        for (int r = 0; r < 4; r++) oa[ni][r] = 0.f;

    const int kmax = 2 * qi + 2;
    load_kv(0, 0);
    load_kv(1, 1);     // kmax >= 2 always

    for (int kb = 0; kb < kmax; kb++) {
        const int s = kb % 3;
        if (kb + 1 < kmax) { CP_WAIT(1); } else { CP_WAIT(0); }
        __syncthreads();
        if (kb + 2 < kmax) load_kv(kb + 2, (kb + 2) % 3);

        const uint32_t sK = sbKV + (uint32_t)s * (KVST * 2);
        const uint32_t sV = sK + 64 * QP * 2;

        // ---- S = Q K^T ----
        float sa[8][4];
#pragma unroll
        for (int ni = 0; ni < 8; ni++)
#pragma unroll
            for (int r = 0; r < 4; r++) sa[ni][r] = 0.f;

#pragma unroll
        for (int ks = 0; ks < 8; ks++) {
            const int kc = ks * 16;
            uint32_t a[4], bf[8][2];
            {
                uint32_t addr = sbQ + (uint32_t)((wq + l7 + lb3 * 8) * QP + kc + lb4 * 8) * 2;
                ldsm4(a[0], a[1], a[2], a[3], addr);
            }
#pragma unroll
            for (int nip = 0; nip < 4; nip++) {
                uint32_t addr = sK + (uint32_t)((nip * 16 + l7 + lb4 * 8) * QP + kc + lb3 * 8) * 2;
                ldsm4(bf[nip*2][0], bf[nip*2][1], bf[nip*2+1][0], bf[nip*2+1][1], addr);
            }
#pragma unroll
            for (int ni = 0; ni < 8; ni++)
                mma_f16(sa[ni], a, bf[ni][0], bf[ni][1]);
        }

        // ---- causal mask ----
        if (kb >= 2 * qi) {
            int r0 = qi * 128 + wq + g;
#pragma unroll
            for (int ni = 0; ni < 8; ni++) {
                int c0 = kb * 64 + ni * 8 + 2 * tig;
                if (c0 > r0)         sa[ni][0] = -INFINITY;
                if (c0 + 1 > r0)     sa[ni][1] = -INFINITY;
                if (c0 > r0 + 8)     sa[ni][2] = -INFINITY;
                if (c0 + 1 > r0 + 8) sa[ni][3] = -INFINITY;
            }
        }

        // ---- online softmax ----
        float mx0 = -INFINITY, mx1 = -INFINITY;
#pragma unroll
        for (int ni = 0; ni < 8; ni++) {
            mx0 = fmaxf(mx0, fmaxf(sa[ni][0], sa[ni][1]));
            mx1 = fmaxf(mx1, fmaxf(sa[ni][2], sa[ni][3]));
        }
        mx0 = fmaxf(mx0, __shfl_xor_sync(0xffffffffu, mx0, 1));
        mx0 = fmaxf(mx0, __shfl_xor_sync(0xffffffffu, mx0, 2));
        mx1 = fmaxf(mx1, __shfl_xor_sync(0xffffffffu, mx1, 1));
        mx1 = fmaxf(mx1, __shfl_xor_sync(0xffffffffu, mx1, 2));

        float mm0 = fmaxf(m0, mx0), mm1 = fmaxf(m1, mx1);
        float sub0 = (mm0 == -INFINITY) ? 0.f : mm0;
        float sub1 = (mm1 == -INFINITY) ? 0.f : mm1;
        float al0 = exp2f(m0 - sub0);
        float al1 = exp2f(m1 - sub1);
        m0 = mm0; m1 = mm1;

        float ls0 = 0.f, ls1 = 0.f;
#pragma unroll
        for (int ni = 0; ni < 8; ni++) {
            float p0 = exp2f(sa[ni][0] - sub0);
            float p1 = exp2f(sa[ni][1] - sub0);
            float p2 = exp2f(sa[ni][2] - sub1);
            float p3 = exp2f(sa[ni][3] - sub1);
            ls0 += p0 + p1; ls1 += p2 + p3;
            P2[(wq + g) * (VP/2) + ni * 4 + tig]     = __floats2half2_rn(p0, p1);
            P2[(wq + g + 8) * (VP/2) + ni * 4 + tig] = __floats2half2_rn(p2, p3);
        }
        ls0 += __shfl_xor_sync(0xffffffffu, ls0, 1);
        ls0 += __shfl_xor_sync(0xffffffffu, ls0, 2);
        ls1 += __shfl_xor_sync(0xffffffffu, ls1, 1);
        ls1 += __shfl_xor_sync(0xffffffffu, ls1, 2);
        l0 = l0 * al0 + ls0;
        l1 = l1 * al1 + ls1;

#pragma unroll
        for (int ni = 0; ni < 16; ni++) {
            oa[ni][0] *= al0; oa[ni][1] *= al0;
            oa[ni][2] *= al1; oa[ni][3] *= al1;
        }
        __syncwarp();

        // ---- O += P @ V ----
#pragma unroll
        for (int ks = 0; ks < 4; ks++) {
            const int kc = ks * 16;
            uint32_t a[4];
            {
                uint32_t addr = sbP + (uint32_t)((wq + l7 + lb3 * 8) * VP + kc + lb4 * 8) * 2;
                ldsm4(a[0], a[1], a[2], a[3], addr);
            }
#pragma unroll
            for (int nip = 0; nip < 8; nip++) {
                uint32_t bf0, bf1, bf2, bf3;
                uint32_t addr = sV + (uint32_t)((kc + l7 + lb3 * 8) * QP + nip * 16 + lb4 * 8) * 2;
                ldsm4t(bf0, bf1, bf2, bf3, addr);
                mma_f16(oa[nip*2],     a, bf0, bf1);
                mma_f16(oa[nip*2 + 1], a, bf2, bf3);
            }
        }
    }

    // ---- epilogue ----
    float inv0 = 1.0f / l0, inv1 = 1.0f / l1;
    __half* Og = O + (size_t)(b * SEQ + qi * 128 + wq) * QDIM + h * HD;
#pragma unroll
    for (int ni = 0; ni < 16; ni++) {
        int col = ni * 8 + 2 * tig;
        *(__half2*)(Og + (size_t)g * QDIM + col) =
            __floats2half2_rn(oa[ni][0] * inv0, oa[ni][1] * inv0);
        *(__half2*)(Og + (size_t)(g + 8) * QDIM + col) =
            __floats2half2_rn(oa[ni][2] * inv1, oa[ni][3] * inv1);
    }
}

// ---------------------------------------------------------------------------
// Launch
// ---------------------------------------------------------------------------
extern "C" void kernel_launch(void* const* d_in, const int* in_sizes, int n_in,
                              void* d_out, int out_size)
{
    const float* query = (const float*)d_in[0];
    const float* key   = (const float*)d_in[1];
    const float* value = (const float*)d_in[2];
    const float* Wq = (const float*)d_in[5];
    const float* Wk = (const float*)d_in[6];
    const float* Wv = (const float*)d_in[7];
    const float* Wo = (const float*)d_in[8];
    float* out = (float*)d_out;

    float *pQ, *pK;
    __half *pAh, *pQh, *pKh, *pVh, *pAOh, *pWqTh, *pWkTh, *pWvTh, *pWoTh;
    cudaGetSymbolAddress((void**)&pQ,    g_Q);
    cudaGetSymbolAddress((void**)&pK,    g_K);
    cudaGetSymbolAddress((void**)&pAh,   g_Ah);
    cudaGetSymbolAddress((void**)&pQh,   g_Qh);
    cudaGetSymbolAddress((void**)&pKh,   g_Kh);
    cudaGetSymbolAddress((void**)&pVh,   g_Vh);
    cudaGetSymbolAddress((void**)&pAOh,  g_AOh);
    cudaGetSymbolAddress((void**)&pWqTh, g_WqTh);
    cudaGetSymbolAddress((void**)&pWkTh, g_WkTh);
    cudaGetSymbolAddress((void**)&pWvTh, g_WvTh);
    cudaGetSymbolAddress((void**)&pWoTh, g_WoTh);

    cudaFuncSetAttribute(gemm_f16<false>, cudaFuncAttributeMaxDynamicSharedMemorySize, GEMM16_SMEM);
    cudaFuncSetAttribute(gemm_f16<true>,  cudaFuncAttributeMaxDynamicSharedMemorySize, GEMM16_SMEM);
    cudaFuncSetAttribute(flash4, cudaFuncAttributeMaxDynamicSharedMemorySize, FL4_SMEM);

    dim3 tb(32, 8);
    transpose_h<<<dim3(QDIM  / 32, EMB / 32), tb>>>(Wq, pWqTh, EMB, QDIM);
    transpose_h<<<dim3(KVDIM / 32, EMB / 32), tb>>>(Wk, pWkTh, EMB, KVDIM);
    transpose_h<<<dim3(KVDIM / 32, EMB / 32), tb>>>(Wv, pWvTh, EMB, KVDIM);
    transpose_h<<<dim3(EMB   / 32, QDIM / 32), tb>>>(Wo, pWoTh, QDIM, EMB);

    const int nact = MROWS * EMB;
    conv_f2h<<<nact / 1024, 256>>>(query, pAh, nact);
    gemm_f16<false><<<dim3(QDIM / 128, MROWS / 128), 256, GEMM16_SMEM>>>(pAh, pWqTh, pQ, MROWS, QDIM, EMB);
    conv_f2h<<<nact / 1024, 256>>>(key, pAh, nact);
    gemm_f16<false><<<dim3(KVDIM / 128, MROWS / 128), 256, GEMM16_SMEM>>>(pAh, pWkTh, pK, MROWS, KVDIM, EMB);
    conv_f2h<<<nact / 1024, 256>>>(value, pAh, nact);
    gemm_f16<true><<<dim3(KVDIM / 128, MROWS / 128), 256, GEMM16_SMEM>>>(pAh, pWvTh, pVh, MROWS, KVDIM, EMB);

    int totq = MROWS * NH * 64;
    rope_h<<<(totq + 255) / 256, 256>>>(pQ, pQh, NH, QSCALE, totq);
    int totk = MROWS * NKVH * 64;
    rope_h<<<(totk + 255) / 256, 256>>>(pK, pKh, NKVH, 1.0f, totk);

    flash4<<<dim3(SEQ / 128, NH, BSZ), 256, FL4_SMEM>>>(pQh, pKh, pVh, pAOh);

    gemm_f16<false><<<dim3(EMB / 128, MROWS / 128), 256, GEMM16_SMEM>>>(pAOh, pWoTh, out, MROWS, EMB, QDIM);
}